// round 1
// baseline (speedup 1.0000x reference)
#include <cuda_runtime.h>
#include <math.h>

// Problem constants
#define V_   32000
#define E_   1024
#define L_   8
#define H_   16
#define B_   2
#define T_   1024
#define D_   64
#define M_   (B_ * T_)      // 2048 rows
#define FF_  (4 * E_)       // 4096
#define QKV3 (3 * E_)       // 3072

// ---------------------------------------------------------------------------
// Scratch (device globals — no allocation allowed in kernel_launch)
// ---------------------------------------------------------------------------
__device__ float g_x[M_ * E_];      // residual stream
__device__ float g_h[M_ * E_];      // LN output
__device__ float g_qkv[M_ * QKV3];  // fused QKV
__device__ float g_y[M_ * E_];      // attention output
__device__ float g_fc[M_ * FF_];    // MLP hidden

// ---------------------------------------------------------------------------
// Embedding: x[b,t,:] = tok_emb[idx[b,t],:] + pos_emb[t,:]
// ---------------------------------------------------------------------------
__global__ void embed_kernel(const int* __restrict__ idx,
                             const float* __restrict__ tok,
                             const float* __restrict__ pos,
                             float* __restrict__ x) {
    int row = blockIdx.x;           // b*T + t
    int t = row % T_;
    int id = idx[row];
    const float* tr = tok + (size_t)id * E_;
    const float* pr = pos + (size_t)t * E_;
    float* xr = x + (size_t)row * E_;
    for (int i = threadIdx.x; i < E_; i += blockDim.x)
        xr[i] = tr[i] + pr[i];
}

// ---------------------------------------------------------------------------
// LayerNorm (two-pass, biased variance as in jnp.var)
// ---------------------------------------------------------------------------
__global__ void lnorm_kernel(const float* __restrict__ x,
                             const float* __restrict__ s,
                             const float* __restrict__ b,
                             float* __restrict__ o) {
    int row = blockIdx.x;
    const float* xr = x + (size_t)row * E_;
    float* orow = o + (size_t)row * E_;
    __shared__ float red[256];
    int tid = threadIdx.x;

    float sum = 0.f;
    for (int i = tid; i < E_; i += 256) sum += xr[i];
    red[tid] = sum;
    __syncthreads();
    for (int off = 128; off > 0; off >>= 1) {
        if (tid < off) red[tid] += red[tid + off];
        __syncthreads();
    }
    float mu = red[0] * (1.0f / E_);
    __syncthreads();

    float vs = 0.f;
    for (int i = tid; i < E_; i += 256) { float d = xr[i] - mu; vs += d * d; }
    red[tid] = vs;
    __syncthreads();
    for (int off = 128; off > 0; off >>= 1) {
        if (tid < off) red[tid] += red[tid + off];
        __syncthreads();
    }
    float inv = rsqrtf(red[0] * (1.0f / E_) + 1e-5f);

    for (int i = tid; i < E_; i += 256)
        orow[i] = (xr[i] - mu) * inv * s[i] + b[i];
}

// ---------------------------------------------------------------------------
// GEMM: C[M,N] = A[M,K] @ W[N,K]^T (+ residual R) (+ exact GELU)
// Tiles: BM=BN=64, BK=16, 256 threads (16x16), 4x4 micro-tile per thread.
// All M/N/K used are divisible by 64/64/16 — no bounds checks in loads.
// Smem row stride 68 floats: 16B-aligned rows for float4 reads, conflict-light.
// ---------------------------------------------------------------------------
template<int GELU>
__global__ void gemm_tn_kernel(const float* __restrict__ A,
                               const float* __restrict__ W,   // [N,K]
                               const float* __restrict__ R,   // residual or null
                               float* __restrict__ C,
                               int N, int K) {
    __shared__ float As[16][68];
    __shared__ float Bs[16][68];
    const int tx = threadIdx.x, ty = threadIdx.y;
    const int tid = ty * 16 + tx;
    const int m0 = blockIdx.y * 64;
    const int n0 = blockIdx.x * 64;

    float acc[4][4] = {};

    for (int k0 = 0; k0 < K; k0 += 16) {
        #pragma unroll
        for (int i = 0; i < 4; i++) {
            int e = tid + i * 256;          // 0..1023
            int r = e >> 4;                  // row within tile (0..63)
            int kk = e & 15;                 // k within tile
            As[kk][r] = A[(size_t)(m0 + r) * K + k0 + kk];
            Bs[kk][r] = W[(size_t)(n0 + r) * K + k0 + kk];
        }
        __syncthreads();
        #pragma unroll
        for (int kk = 0; kk < 16; kk++) {
            float4 a4 = *(const float4*)&As[kk][ty * 4];
            float4 b4 = *(const float4*)&Bs[kk][tx * 4];
            float av[4] = {a4.x, a4.y, a4.z, a4.w};
            float bv[4] = {b4.x, b4.y, b4.z, b4.w};
            #pragma unroll
            for (int i = 0; i < 4; i++)
                #pragma unroll
                for (int j = 0; j < 4; j++)
                    acc[i][j] += av[i] * bv[j];
        }
        __syncthreads();
    }

    #pragma unroll
    for (int i = 0; i < 4; i++) {
        int m = m0 + ty * 4 + i;
        #pragma unroll
        for (int j = 0; j < 4; j++) {
            int n = n0 + tx * 4 + j;
            float v = acc[i][j];
            if (R) v += R[(size_t)m * N + n];
            if (GELU) v = 0.5f * v * (1.0f + erff(v * 0.70710678118654752f));
            C[(size_t)m * N + n] = v;
        }
    }
}

// ---------------------------------------------------------------------------
// Causal attention. One block per (q-position t, head h, batch b).
// 128 threads: score pass over k<=t, block softmax, then 64 threads do the
// p @ V accumulation (one output dim each).
// qkv layout: [B*T, 3E], q at +0, k at +E, v at +2E, head h at cols h*D..
// ---------------------------------------------------------------------------
__global__ void attn_kernel(const float* __restrict__ qkv,
                            float* __restrict__ y) {
    const int t = blockIdx.x, h = blockIdx.y, b = blockIdx.z;
    const int tid = threadIdx.x;   // 128

    __shared__ float qv[D_];
    __shared__ float sc[T_];
    __shared__ float red[128];

    const size_t rowQ = (size_t)(b * T_ + t) * QKV3;
    if (tid < D_) qv[tid] = qkv[rowQ + h * D_ + tid];
    __syncthreads();

    const float scale = 0.125f;   // 1/sqrt(64)

    // Scores + local max
    float lmax = -1e30f;
    for (int k = tid; k <= t; k += 128) {
        const float* kp = qkv + (size_t)(b * T_ + k) * QKV3 + E_ + h * D_;
        float s = 0.f;
        #pragma unroll
        for (int d = 0; d < D_; d++) s += qv[d] * kp[d];
        s *= scale;
        sc[k] = s;
        lmax = fmaxf(lmax, s);
    }
    red[tid] = lmax;
    __syncthreads();
    for (int off = 64; off > 0; off >>= 1) {
        if (tid < off) red[tid] = fmaxf(red[tid], red[tid + off]);
        __syncthreads();
    }
    float mx = red[0];
    __syncthreads();

    // Exponentiate + sum
    float lsum = 0.f;
    for (int k = tid; k <= t; k += 128) {
        float e = __expf(sc[k] - mx);
        sc[k] = e;
        lsum += e;
    }
    red[tid] = lsum;
    __syncthreads();
    for (int off = 64; off > 0; off >>= 1) {
        if (tid < off) red[tid] += red[tid + off];
        __syncthreads();
    }
    float inv = 1.0f / red[0];
    __syncthreads();

    // p @ V: 64 threads, one output dim each
    if (tid < D_) {
        float acc = 0.f;
        const float* vbase = qkv + (size_t)b * T_ * QKV3 + 2 * E_ + h * D_ + tid;
        for (int k = 0; k <= t; k++)
            acc += sc[k] * vbase[(size_t)k * QKV3];
        y[(size_t)(b * T_ + t) * E_ + h * D_ + tid] = acc * inv;
    }
}

// ---------------------------------------------------------------------------
// Launch
// ---------------------------------------------------------------------------
extern "C" void kernel_launch(void* const* d_in, const int* in_sizes, int n_in,
                              void* d_out, int out_size) {
    const int*   idx    = (const int*)  d_in[0];
    const float* tok    = (const float*)d_in[1];
    const float* pos    = (const float*)d_in[2];
    const float* qkv_w  = (const float*)d_in[3];   // [L,3E,E]
    const float* proj_w = (const float*)d_in[4];   // [L,E,E]
    const float* fc_w   = (const float*)d_in[5];   // [L,4E,E]
    const float* fcp_w  = (const float*)d_in[6];   // [L,E,4E]
    const float* ln1s   = (const float*)d_in[7];
    const float* ln1b   = (const float*)d_in[8];
    const float* ln2s   = (const float*)d_in[9];
    const float* ln2b   = (const float*)d_in[10];
    const float* lnfs   = (const float*)d_in[11];
    const float* lnfb   = (const float*)d_in[12];
    float* out = (float*)d_out;

    float *x, *h, *qkv, *y, *fc;
    cudaGetSymbolAddress((void**)&x,   g_x);
    cudaGetSymbolAddress((void**)&h,   g_h);
    cudaGetSymbolAddress((void**)&qkv, g_qkv);
    cudaGetSymbolAddress((void**)&y,   g_y);
    cudaGetSymbolAddress((void**)&fc,  g_fc);

    const dim3 gblk(16, 16);

    embed_kernel<<<M_, 256>>>(idx, tok, pos, x);

    for (int l = 0; l < L_; l++) {
        // LN1 -> h
        lnorm_kernel<<<M_, 256>>>(x, ln1s + (size_t)l * E_, ln1b + (size_t)l * E_, h);
        // QKV = h @ Wqkv^T
        gemm_tn_kernel<0><<<dim3(QKV3 / 64, M_ / 64), gblk>>>(
            h, qkv_w + (size_t)l * QKV3 * E_, nullptr, qkv, QKV3, E_);
        // attention -> y
        attn_kernel<<<dim3(T_, H_, B_), 128>>>(qkv, y);
        // x = x + y @ Wproj^T
        gemm_tn_kernel<0><<<dim3(E_ / 64, M_ / 64), gblk>>>(
            y, proj_w + (size_t)l * E_ * E_, x, x, E_, E_);
        // LN2 -> h
        lnorm_kernel<<<M_, 256>>>(x, ln2s + (size_t)l * E_, ln2b + (size_t)l * E_, h);
        // fc = gelu(h @ Wfc^T)
        gemm_tn_kernel<1><<<dim3(FF_ / 64, M_ / 64), gblk>>>(
            h, fc_w + (size_t)l * FF_ * E_, nullptr, fc, FF_, E_);
        // x = x + fc @ Wfcp^T
        gemm_tn_kernel<0><<<dim3(E_ / 64, M_ / 64), gblk>>>(
            fc, fcp_w + (size_t)l * E_ * FF_, x, x, E_, FF_);
    }

    // Final LN -> h, logits = h @ tok_emb^T
    lnorm_kernel<<<M_, 256>>>(x, lnfs, lnfb, h);
    gemm_tn_kernel<0><<<dim3(V_ / 64, M_ / 64), gblk>>>(
        h, tok, nullptr, out, V_, E_);
}

// round 3
// speedup vs baseline: 1.2541x; 1.2541x over previous
#include <cuda_runtime.h>
#include <cuda_bf16.h>
#include <math.h>
#include <stdint.h>

// Problem constants
#define V_   32000
#define E_   1024
#define L_   8
#define H_   16
#define B_   2
#define T_   1024
#define D_   64
#define M_   (B_ * T_)      // 2048 rows
#define FF_  (4 * E_)       // 4096
#define QKV3 (3 * E_)       // 3072

typedef __nv_bfloat16 bf16;

// ---------------------------------------------------------------------------
// Scratch (device globals — no allocation allowed in kernel_launch)
// ---------------------------------------------------------------------------
__device__ float g_x[M_ * E_];          // residual stream (fp32)
__device__ float g_qkv[M_ * QKV3];      // fused QKV (fp32, for attention)
__device__ bf16  g_b1h[M_ * E_];        // activation buf1 hi
__device__ bf16  g_b1l[M_ * E_];        // activation buf1 lo
__device__ bf16  g_b2h[M_ * FF_];       // activation buf2 hi (MLP hidden)
__device__ bf16  g_b2l[M_ * FF_];       // activation buf2 lo
// bf16 split weights
__device__ bf16  g_wqkv_h[L_ * QKV3 * E_];
__device__ bf16  g_wqkv_l[L_ * QKV3 * E_];
__device__ bf16  g_wproj_h[L_ * E_ * E_];
__device__ bf16  g_wproj_l[L_ * E_ * E_];
__device__ bf16  g_wfc_h[L_ * FF_ * E_];
__device__ bf16  g_wfc_l[L_ * FF_ * E_];
__device__ bf16  g_wfcp_h[L_ * E_ * FF_];
__device__ bf16  g_wfcp_l[L_ * E_ * FF_];
__device__ bf16  g_tok_h[V_ * E_];
__device__ bf16  g_tok_l[V_ * E_];

// ---------------------------------------------------------------------------
// PTX helpers (base-target features only: cp.async, ldmatrix, mma.sync)
// ---------------------------------------------------------------------------
__device__ __forceinline__ uint32_t smem_u32(const void* p) {
    uint32_t a;
    asm("{ .reg .u64 t; cvta.to.shared.u64 t, %1; cvt.u32.u64 %0, t; }"
        : "=r"(a) : "l"(p));
    return a;
}

#define SWZ128(o) ((o) ^ (((o) >> 3) & 0x70))

__device__ __forceinline__ void cp_async16(uint32_t dst, const void* src) {
    asm volatile("cp.async.cg.shared.global [%0], [%1], 16;\n"
                 :: "r"(dst), "l"(src) : "memory");
}
__device__ __forceinline__ void cp_commit() {
    asm volatile("cp.async.commit_group;\n" ::: "memory");
}
template <int N>
__device__ __forceinline__ void cp_wait() {
    asm volatile("cp.async.wait_group %0;\n" :: "n"(N) : "memory");
}
__device__ __forceinline__ void ldsm_x4(uint32_t* r, uint32_t addr) {
    asm volatile("ldmatrix.sync.aligned.m8n8.x4.shared.b16 {%0,%1,%2,%3}, [%4];"
                 : "=r"(r[0]), "=r"(r[1]), "=r"(r[2]), "=r"(r[3]) : "r"(addr));
}
__device__ __forceinline__ void ldsm_x2(uint32_t* r, uint32_t addr) {
    asm volatile("ldmatrix.sync.aligned.m8n8.x2.shared.b16 {%0,%1}, [%2];"
                 : "=r"(r[0]), "=r"(r[1]) : "r"(addr));
}
__device__ __forceinline__ void mma16816(float* d, const uint32_t* a,
                                         const uint32_t* b) {
    asm volatile(
        "mma.sync.aligned.m16n8k16.row.col.f32.bf16.bf16.f32 "
        "{%0,%1,%2,%3}, {%4,%5,%6,%7}, {%8,%9}, {%0,%1,%2,%3};"
        : "+f"(d[0]), "+f"(d[1]), "+f"(d[2]), "+f"(d[3])
        : "r"(a[0]), "r"(a[1]), "r"(a[2]), "r"(a[3]), "r"(b[0]), "r"(b[1]));
}

__device__ __forceinline__ void split_store(float v, bf16* hp, bf16* lp) {
    bf16 h = __float2bfloat16(v);
    *hp = h;
    *lp = __float2bfloat16(v - __bfloat162float(h));
}

// ---------------------------------------------------------------------------
// Weight split: fp32 -> (hi, lo) bf16, float4 granularity
// ---------------------------------------------------------------------------
__global__ void split_kernel(const float* __restrict__ x,
                             bf16* __restrict__ hi, bf16* __restrict__ lo,
                             int n4) {
    int i = blockIdx.x * blockDim.x + threadIdx.x;
    if (i >= n4) return;
    float4 v = ((const float4*)x)[i];
    bf16 h0 = __float2bfloat16(v.x), h1 = __float2bfloat16(v.y);
    bf16 h2 = __float2bfloat16(v.z), h3 = __float2bfloat16(v.w);
    bf16 l0 = __float2bfloat16(v.x - __bfloat162float(h0));
    bf16 l1 = __float2bfloat16(v.y - __bfloat162float(h1));
    bf16 l2 = __float2bfloat16(v.z - __bfloat162float(h2));
    bf16 l3 = __float2bfloat16(v.w - __bfloat162float(h3));
    uint32_t hp0 = (uint32_t)__bfloat16_as_ushort(h0) | ((uint32_t)__bfloat16_as_ushort(h1) << 16);
    uint32_t hp1 = (uint32_t)__bfloat16_as_ushort(h2) | ((uint32_t)__bfloat16_as_ushort(h3) << 16);
    uint32_t lp0 = (uint32_t)__bfloat16_as_ushort(l0) | ((uint32_t)__bfloat16_as_ushort(l1) << 16);
    uint32_t lp1 = (uint32_t)__bfloat16_as_ushort(l2) | ((uint32_t)__bfloat16_as_ushort(l3) << 16);
    ((uint2*)hi)[i] = make_uint2(hp0, hp1);
    ((uint2*)lo)[i] = make_uint2(lp0, lp1);
}

// ---------------------------------------------------------------------------
// Embedding (fp32 residual stream)
// ---------------------------------------------------------------------------
__global__ void embed_kernel(const int* __restrict__ idx,
                             const float* __restrict__ tok,
                             const float* __restrict__ pos,
                             float* __restrict__ x) {
    int row = blockIdx.x;
    int t = row % T_;
    int id = idx[row];
    const float* tr = tok + (size_t)id * E_;
    const float* pr = pos + (size_t)t * E_;
    float* xr = x + (size_t)row * E_;
    for (int i = threadIdx.x; i < E_; i += blockDim.x)
        xr[i] = tr[i] + pr[i];
}

// ---------------------------------------------------------------------------
// LayerNorm -> (hi, lo) bf16 output
// ---------------------------------------------------------------------------
__global__ void lnorm_split_kernel(const float* __restrict__ x,
                                   const float* __restrict__ s,
                                   const float* __restrict__ b,
                                   bf16* __restrict__ oh,
                                   bf16* __restrict__ ol) {
    int row = blockIdx.x;
    const float* xr = x + (size_t)row * E_;
    __shared__ float red[256];
    int tid = threadIdx.x;

    float sum = 0.f;
    for (int i = tid; i < E_; i += 256) sum += xr[i];
    red[tid] = sum;
    __syncthreads();
    for (int off = 128; off > 0; off >>= 1) {
        if (tid < off) red[tid] += red[tid + off];
        __syncthreads();
    }
    float mu = red[0] * (1.0f / E_);
    __syncthreads();

    float vs = 0.f;
    for (int i = tid; i < E_; i += 256) { float d = xr[i] - mu; vs += d * d; }
    red[tid] = vs;
    __syncthreads();
    for (int off = 128; off > 0; off >>= 1) {
        if (tid < off) red[tid] += red[tid + off];
        __syncthreads();
    }
    float inv = rsqrtf(red[0] * (1.0f / E_) + 1e-5f);

    for (int i = tid; i < E_; i += 256) {
        float v = (xr[i] - mu) * inv * s[i] + b[i];
        split_store(v, &oh[(size_t)row * E_ + i], &ol[(size_t)row * E_ + i]);
    }
}

// ---------------------------------------------------------------------------
// Causal attention (fp32) -> y as (hi, lo) bf16
// ---------------------------------------------------------------------------
__global__ void attn_kernel(const float* __restrict__ qkv,
                            bf16* __restrict__ yh, bf16* __restrict__ yl) {
    const int t = blockIdx.x, h = blockIdx.y, b = blockIdx.z;
    const int tid = threadIdx.x;   // 128

    __shared__ float qv[D_];
    __shared__ float sc[T_];
    __shared__ float red[128];

    const size_t rowQ = (size_t)(b * T_ + t) * QKV3;
    if (tid < D_) qv[tid] = qkv[rowQ + h * D_ + tid];
    __syncthreads();

    const float scale = 0.125f;
    float lmax = -1e30f;
    for (int k = tid; k <= t; k += 128) {
        const float* kp = qkv + (size_t)(b * T_ + k) * QKV3 + E_ + h * D_;
        float s = 0.f;
        #pragma unroll
        for (int d = 0; d < D_; d++) s += qv[d] * kp[d];
        s *= scale;
        sc[k] = s;
        lmax = fmaxf(lmax, s);
    }
    red[tid] = lmax;
    __syncthreads();
    for (int off = 64; off > 0; off >>= 1) {
        if (tid < off) red[tid] = fmaxf(red[tid], red[tid + off]);
        __syncthreads();
    }
    float mx = red[0];
    __syncthreads();

    float lsum = 0.f;
    for (int k = tid; k <= t; k += 128) {
        float e = __expf(sc[k] - mx);
        sc[k] = e;
        lsum += e;
    }
    red[tid] = lsum;
    __syncthreads();
    for (int off = 64; off > 0; off >>= 1) {
        if (tid < off) red[tid] += red[tid + off];
        __syncthreads();
    }
    float inv = 1.0f / red[0];
    __syncthreads();

    if (tid < D_) {
        float acc = 0.f;
        const float* vbase = qkv + (size_t)b * T_ * QKV3 + 2 * E_ + h * D_ + tid;
        for (int k = 0; k <= t; k++)
            acc += sc[k] * vbase[(size_t)k * QKV3];
        float v = acc * inv;
        size_t off = (size_t)(b * T_ + t) * E_ + h * D_ + tid;
        split_store(v, &yh[off], &yl[off]);
    }
}

// ---------------------------------------------------------------------------
// HMMA bf16x3 GEMM: C[M,N] = A[M,K] @ W[N,K]^T
//   A as (Ahi, Alo), W as (Bhi, Blo); accumulates Ahi*Bhi + Ahi*Blo + Alo*Bhi
//   in fp32 registers via mma.sync.m16n8k16 (base-target legacy HMMA).
//   CTA tile 128x128, K-chunks of 64, 256 threads (8 warps, 2x4 grid,
//   warp tile 64x32). Double-buffered cp.async into SW128-swizzled SMEM.
// Epilogue: optional residual add (R), optional exact GELU,
//   output either fp32 (Cf) or bf16 hi/lo re-split (Chi/Clo).
// SMEM: 2 stages x (Ah|Al|Bh|Bl) x 128 rows x 128B = 131072 bytes.
// ---------------------------------------------------------------------------
#define GEMM_SMEM_BYTES (2 * 4 * 128 * 128)

__device__ __forceinline__ void load_row8(uint32_t smem_tile,
                                          const bf16* __restrict__ g,
                                          int row0, int K, int k0, int r) {
    const char* gp = (const char*)(g + (size_t)(row0 + r) * K + k0);
    uint32_t rb = (uint32_t)r * 128;
    #pragma unroll
    for (int j = 0; j < 8; j++)
        cp_async16(smem_tile + SWZ128(rb + j * 16), gp + j * 16);
}

template<bool GELU, bool RES, bool OUT32>
__global__ void __launch_bounds__(256, 1)
gemm_hmma_kernel(const bf16* __restrict__ Ahi, const bf16* __restrict__ Alo,
                 const bf16* __restrict__ Bhi, const bf16* __restrict__ Blo,
                 const float* __restrict__ R, float* __restrict__ Cf,
                 bf16* __restrict__ Chi, bf16* __restrict__ Clo,
                 int N, int K) {
    extern __shared__ char smem[];
    const uint32_t sb = smem_u32(smem);

    const int tid = threadIdx.x;
    const int lane = tid & 31;
    const int wid = tid >> 5;
    const int wm = (wid >> 2) * 64;     // warp M offset within CTA tile
    const int wn = (wid & 3) * 32;      // warp N offset within CTA tile
    const int m0 = blockIdx.y * 128;
    const int n0 = blockIdx.x * 128;
    const int nchunks = K >> 6;

    // loader: thread handles one A row and one B row of either hi (lt=0) or
    // lo (lt=1) tiles.
    const int lr = tid & 127;
    const int lt = tid >> 7;
    const bf16* Ag = lt ? Alo : Ahi;
    const bf16* Bg = lt ? Blo : Bhi;
    const uint32_t aoff = (uint32_t)lt * 16384;          // Ah=0 / Al=16384
    const uint32_t boff = 32768 + (uint32_t)lt * 16384;  // Bh / Bl

    float acc[4][4][4];
    #pragma unroll
    for (int i = 0; i < 4; i++)
        #pragma unroll
        for (int j = 0; j < 4; j++)
            #pragma unroll
            for (int q = 0; q < 4; q++) acc[i][j][q] = 0.f;

    // preload chunk 0 into stage 0
    load_row8(sb + aoff, Ag, m0, K, 0, lr);
    load_row8(sb + boff, Bg, n0, K, 0, lr);
    cp_commit();

    // precomputed ldmatrix lane offsets (within a 128B swizzled row tile)
    const uint32_t a_row = wm + (lane & 15);
    const uint32_t a_cb  = (uint32_t)((lane >> 4) << 4);
    const uint32_t b_cb  = (uint32_t)(((lane >> 3) & 1) << 4);

    for (int c = 0; c < nchunks; c++) {
        const uint32_t st = sb + (uint32_t)(c & 1) * 65536;

        cp_wait<0>();
        __syncthreads();

        if (c + 1 < nchunks) {
            const uint32_t sn = sb + (uint32_t)((c + 1) & 1) * 65536;
            load_row8(sn + aoff, Ag, m0, K, (c + 1) << 6, lr);
            load_row8(sn + boff, Bg, n0, K, (c + 1) << 6, lr);
            cp_commit();
        }

        const uint32_t aAh = st, aAl = st + 16384;
        const uint32_t aBh = st + 32768, aBl = st + 49152;

        #pragma unroll
        for (int ks = 0; ks < 4; ks++) {
            const uint32_t kb = (uint32_t)ks * 32;   // 16 bf16 = 32B per k-step
            uint32_t ah[4][4], al[4][4], bh[4][2], bl[4][2];
            #pragma unroll
            for (int mi = 0; mi < 4; mi++) {
                uint32_t off = SWZ128((a_row + mi * 16) * 128 + kb + a_cb);
                ldsm_x4(ah[mi], aAh + off);
                ldsm_x4(al[mi], aAl + off);
            }
            #pragma unroll
            for (int ni = 0; ni < 4; ni++) {
                uint32_t off = SWZ128((wn + ni * 8 + (lane & 7)) * 128 + kb + b_cb);
                ldsm_x2(bh[ni], aBh + off);
                ldsm_x2(bl[ni], aBl + off);
            }
            #pragma unroll
            for (int mi = 0; mi < 4; mi++)
                #pragma unroll
                for (int ni = 0; ni < 4; ni++) {
                    mma16816(acc[mi][ni], ah[mi], bh[ni]);
                    mma16816(acc[mi][ni], ah[mi], bl[ni]);
                    mma16816(acc[mi][ni], al[mi], bh[ni]);
                }
        }
        __syncthreads();
    }

    // ---------------- epilogue ----------------
    const int er = lane >> 2;          // row within 16-row tile (0..7)
    const int ec = (lane & 3) * 2;     // col within 8-col tile

    #pragma unroll
    for (int mi = 0; mi < 4; mi++) {
        #pragma unroll
        for (int ni = 0; ni < 4; ni++) {
            const int row = m0 + wm + mi * 16 + er;
            const int col = n0 + wn + ni * 8 + ec;
            float v0 = acc[mi][ni][0], v1 = acc[mi][ni][1];
            float v2 = acc[mi][ni][2], v3 = acc[mi][ni][3];
            if (RES) {
                float2 r0 = *(const float2*)(R + (size_t)row * N + col);
                float2 r1 = *(const float2*)(R + (size_t)(row + 8) * N + col);
                v0 += r0.x; v1 += r0.y; v2 += r1.x; v3 += r1.y;
            }
            if (GELU) {
                v0 = 0.5f * v0 * (1.0f + erff(v0 * 0.70710678118654752f));
                v1 = 0.5f * v1 * (1.0f + erff(v1 * 0.70710678118654752f));
                v2 = 0.5f * v2 * (1.0f + erff(v2 * 0.70710678118654752f));
                v3 = 0.5f * v3 * (1.0f + erff(v3 * 0.70710678118654752f));
            }
            if (OUT32) {
                *(float2*)(Cf + (size_t)row * N + col) = make_float2(v0, v1);
                *(float2*)(Cf + (size_t)(row + 8) * N + col) = make_float2(v2, v3);
            } else {
                bf16 h0 = __float2bfloat16(v0), h1 = __float2bfloat16(v1);
                bf16 h2 = __float2bfloat16(v2), h3 = __float2bfloat16(v3);
                bf16 l0 = __float2bfloat16(v0 - __bfloat162float(h0));
                bf16 l1 = __float2bfloat16(v1 - __bfloat162float(h1));
                bf16 l2 = __float2bfloat16(v2 - __bfloat162float(h2));
                bf16 l3 = __float2bfloat16(v3 - __bfloat162float(h3));
                *(uint32_t*)(Chi + (size_t)row * N + col) =
                    (uint32_t)__bfloat16_as_ushort(h0) | ((uint32_t)__bfloat16_as_ushort(h1) << 16);
                *(uint32_t*)(Chi + (size_t)(row + 8) * N + col) =
                    (uint32_t)__bfloat16_as_ushort(h2) | ((uint32_t)__bfloat16_as_ushort(h3) << 16);
                *(uint32_t*)(Clo + (size_t)row * N + col) =
                    (uint32_t)__bfloat16_as_ushort(l0) | ((uint32_t)__bfloat16_as_ushort(l1) << 16);
                *(uint32_t*)(Clo + (size_t)(row + 8) * N + col) =
                    (uint32_t)__bfloat16_as_ushort(l2) | ((uint32_t)__bfloat16_as_ushort(l3) << 16);
            }
        }
    }
}

// ---------------------------------------------------------------------------
// Launch
// ---------------------------------------------------------------------------
extern "C" void kernel_launch(void* const* d_in, const int* in_sizes, int n_in,
                              void* d_out, int out_size) {
    const int*   idx    = (const int*)  d_in[0];
    const float* tok    = (const float*)d_in[1];
    const float* pos    = (const float*)d_in[2];
    const float* qkv_w  = (const float*)d_in[3];   // [L,3E,E]
    const float* proj_w = (const float*)d_in[4];   // [L,E,E]
    const float* fc_w   = (const float*)d_in[5];   // [L,4E,E]
    const float* fcp_w  = (const float*)d_in[6];   // [L,E,4E]
    const float* ln1s   = (const float*)d_in[7];
    const float* ln1b   = (const float*)d_in[8];
    const float* ln2s   = (const float*)d_in[9];
    const float* ln2b   = (const float*)d_in[10];
    const float* lnfs   = (const float*)d_in[11];
    const float* lnfb   = (const float*)d_in[12];
    float* out = (float*)d_out;

    float *x, *qkv;
    bf16 *b1h, *b1l, *b2h, *b2l;
    bf16 *wqkvh, *wqkvl, *wprojh, *wprojl, *wfch, *wfcl, *wfcph, *wfcpl, *tokh, *tokl;
    cudaGetSymbolAddress((void**)&x,     g_x);
    cudaGetSymbolAddress((void**)&qkv,   g_qkv);
    cudaGetSymbolAddress((void**)&b1h,   g_b1h);
    cudaGetSymbolAddress((void**)&b1l,   g_b1l);
    cudaGetSymbolAddress((void**)&b2h,   g_b2h);
    cudaGetSymbolAddress((void**)&b2l,   g_b2l);
    cudaGetSymbolAddress((void**)&wqkvh, g_wqkv_h);
    cudaGetSymbolAddress((void**)&wqkvl, g_wqkv_l);
    cudaGetSymbolAddress((void**)&wprojh,g_wproj_h);
    cudaGetSymbolAddress((void**)&wprojl,g_wproj_l);
    cudaGetSymbolAddress((void**)&wfch,  g_wfc_h);
    cudaGetSymbolAddress((void**)&wfcl,  g_wfc_l);
    cudaGetSymbolAddress((void**)&wfcph, g_wfcp_h);
    cudaGetSymbolAddress((void**)&wfcpl, g_wfcp_l);
    cudaGetSymbolAddress((void**)&tokh,  g_tok_h);
    cudaGetSymbolAddress((void**)&tokl,  g_tok_l);

    cudaFuncSetAttribute(gemm_hmma_kernel<false, false, true>,
                         cudaFuncAttributeMaxDynamicSharedMemorySize, GEMM_SMEM_BYTES);
    cudaFuncSetAttribute(gemm_hmma_kernel<false, true, true>,
                         cudaFuncAttributeMaxDynamicSharedMemorySize, GEMM_SMEM_BYTES);
    cudaFuncSetAttribute(gemm_hmma_kernel<true, false, false>,
                         cudaFuncAttributeMaxDynamicSharedMemorySize, GEMM_SMEM_BYTES);

    // weight splits (fp32 -> bf16 hi/lo)
    {
        int n4;
        n4 = L_ * QKV3 * E_ / 4;
        split_kernel<<<(n4 + 255) / 256, 256>>>(qkv_w, wqkvh, wqkvl, n4);
        n4 = L_ * E_ * E_ / 4;
        split_kernel<<<(n4 + 255) / 256, 256>>>(proj_w, wprojh, wprojl, n4);
        n4 = L_ * FF_ * E_ / 4;
        split_kernel<<<(n4 + 255) / 256, 256>>>(fc_w, wfch, wfcl, n4);
        n4 = L_ * E_ * FF_ / 4;
        split_kernel<<<(n4 + 255) / 256, 256>>>(fcp_w, wfcph, wfcpl, n4);
        n4 = V_ * E_ / 4;
        split_kernel<<<(n4 + 255) / 256, 256>>>(tok, tokh, tokl, n4);
    }

    embed_kernel<<<M_, 256>>>(idx, tok, pos, x);

    for (int l = 0; l < L_; l++) {
        // LN1 -> buf1 (hi/lo)
        lnorm_split_kernel<<<M_, 256>>>(x, ln1s + (size_t)l * E_, ln1b + (size_t)l * E_, b1h, b1l);
        // QKV = h @ Wqkv^T -> fp32
        gemm_hmma_kernel<false, false, true><<<dim3(QKV3 / 128, M_ / 128), 256, GEMM_SMEM_BYTES>>>(
            b1h, b1l, wqkvh + (size_t)l * QKV3 * E_, wqkvl + (size_t)l * QKV3 * E_,
            nullptr, qkv, nullptr, nullptr, QKV3, E_);
        // attention -> y (hi/lo into buf1)
        attn_kernel<<<dim3(T_, H_, B_), 128>>>(qkv, b1h, b1l);
        // x = x + y @ Wproj^T
        gemm_hmma_kernel<false, true, true><<<dim3(E_ / 128, M_ / 128), 256, GEMM_SMEM_BYTES>>>(
            b1h, b1l, wprojh + (size_t)l * E_ * E_, wprojl + (size_t)l * E_ * E_,
            x, x, nullptr, nullptr, E_, E_);
        // LN2 -> buf1
        lnorm_split_kernel<<<M_, 256>>>(x, ln2s + (size_t)l * E_, ln2b + (size_t)l * E_, b1h, b1l);
        // fc = gelu(h @ Wfc^T) -> buf2 (hi/lo)
        gemm_hmma_kernel<true, false, false><<<dim3(FF_ / 128, M_ / 128), 256, GEMM_SMEM_BYTES>>>(
            b1h, b1l, wfch + (size_t)l * FF_ * E_, wfcl + (size_t)l * FF_ * E_,
            nullptr, nullptr, b2h, b2l, FF_, E_);
        // x = x + fc @ Wfcp^T
        gemm_hmma_kernel<false, true, true><<<dim3(E_ / 128, M_ / 128), 256, GEMM_SMEM_BYTES>>>(
            b2h, b2l, wfcph + (size_t)l * E_ * FF_, wfcpl + (size_t)l * E_ * FF_,
            x, x, nullptr, nullptr, E_, FF_);
    }

    // Final LN -> buf1, logits = h @ tok_emb^T
    lnorm_split_kernel<<<M_, 256>>>(x, lnfs, lnfb, b1h, b1l);
    gemm_hmma_kernel<false, false, true><<<dim3(V_ / 128, M_ / 128), 256, GEMM_SMEM_BYTES>>>(
        b1h, b1l, tokh, tokl, nullptr, out, nullptr, nullptr, V_, E_);
}

// round 4
// speedup vs baseline: 4.7685x; 3.8023x over previous
#include <cuda_runtime.h>
#include <cuda_bf16.h>
#include <math.h>
#include <stdint.h>

// Problem constants
#define V_   32000
#define E_   1024
#define L_   8
#define H_   16
#define B_   2
#define T_   1024
#define D_   64
#define M_   (B_ * T_)      // 2048 rows
#define FF_  (4 * E_)       // 4096
#define QKV3 (3 * E_)       // 3072

typedef __nv_bfloat16 bf16;

// ---------------------------------------------------------------------------
// Scratch (device globals — no allocation allowed in kernel_launch)
// ---------------------------------------------------------------------------
__device__ float g_x[M_ * E_];          // residual stream (fp32)
__device__ float g_qkv[M_ * QKV3];      // fused QKV (fp32, for attention)
__device__ bf16  g_b1h[M_ * E_];        // activation buf1 hi
__device__ bf16  g_b1l[M_ * E_];        // activation buf1 lo
__device__ bf16  g_b2h[M_ * FF_];       // activation buf2 hi (MLP hidden)
__device__ bf16  g_b2l[M_ * FF_];       // activation buf2 lo
// bf16 split weights
__device__ bf16  g_wqkv_h[L_ * QKV3 * E_];
__device__ bf16  g_wqkv_l[L_ * QKV3 * E_];
__device__ bf16  g_wproj_h[L_ * E_ * E_];
__device__ bf16  g_wproj_l[L_ * E_ * E_];
__device__ bf16  g_wfc_h[L_ * FF_ * E_];
__device__ bf16  g_wfc_l[L_ * FF_ * E_];
__device__ bf16  g_wfcp_h[L_ * E_ * FF_];
__device__ bf16  g_wfcp_l[L_ * E_ * FF_];
__device__ bf16  g_tok_h[V_ * E_];
__device__ bf16  g_tok_l[V_ * E_];

// ---------------------------------------------------------------------------
// PTX helpers (base-target features only: cp.async, ldmatrix, mma.sync)
// ---------------------------------------------------------------------------
__device__ __forceinline__ uint32_t smem_u32(const void* p) {
    uint32_t a;
    asm("{ .reg .u64 t; cvta.to.shared.u64 t, %1; cvt.u32.u64 %0, t; }"
        : "=r"(a) : "l"(p));
    return a;
}

#define SWZ128(o) ((o) ^ (((o) >> 3) & 0x70))

__device__ __forceinline__ void cp_async16(uint32_t dst, const void* src) {
    asm volatile("cp.async.cg.shared.global [%0], [%1], 16;\n"
                 :: "r"(dst), "l"(src) : "memory");
}
__device__ __forceinline__ void cp_commit() {
    asm volatile("cp.async.commit_group;\n" ::: "memory");
}
template <int N>
__device__ __forceinline__ void cp_wait() {
    asm volatile("cp.async.wait_group %0;\n" :: "n"(N) : "memory");
}
__device__ __forceinline__ void ldsm_x4(uint32_t* r, uint32_t addr) {
    asm volatile("ldmatrix.sync.aligned.m8n8.x4.shared.b16 {%0,%1,%2,%3}, [%4];"
                 : "=r"(r[0]), "=r"(r[1]), "=r"(r[2]), "=r"(r[3]) : "r"(addr));
}
__device__ __forceinline__ void ldsm_x2(uint32_t* r, uint32_t addr) {
    asm volatile("ldmatrix.sync.aligned.m8n8.x2.shared.b16 {%0,%1}, [%2];"
                 : "=r"(r[0]), "=r"(r[1]) : "r"(addr));
}
__device__ __forceinline__ void mma16816(float* d, const uint32_t* a,
                                         const uint32_t* b) {
    asm volatile(
        "mma.sync.aligned.m16n8k16.row.col.f32.bf16.bf16.f32 "
        "{%0,%1,%2,%3}, {%4,%5,%6,%7}, {%8,%9}, {%0,%1,%2,%3};"
        : "+f"(d[0]), "+f"(d[1]), "+f"(d[2]), "+f"(d[3])
        : "r"(a[0]), "r"(a[1]), "r"(a[2]), "r"(a[3]), "r"(b[0]), "r"(b[1]));
}

__device__ __forceinline__ void split_store(float v, bf16* hp, bf16* lp) {
    bf16 h = __float2bfloat16(v);
    *hp = h;
    *lp = __float2bfloat16(v - __bfloat162float(h));
}

// ---------------------------------------------------------------------------
// Weight split: fp32 -> (hi, lo) bf16, float4 granularity
// ---------------------------------------------------------------------------
__global__ void split_kernel(const float* __restrict__ x,
                             bf16* __restrict__ hi, bf16* __restrict__ lo,
                             int n4) {
    int i = blockIdx.x * blockDim.x + threadIdx.x;
    if (i >= n4) return;
    float4 v = ((const float4*)x)[i];
    bf16 h0 = __float2bfloat16(v.x), h1 = __float2bfloat16(v.y);
    bf16 h2 = __float2bfloat16(v.z), h3 = __float2bfloat16(v.w);
    bf16 l0 = __float2bfloat16(v.x - __bfloat162float(h0));
    bf16 l1 = __float2bfloat16(v.y - __bfloat162float(h1));
    bf16 l2 = __float2bfloat16(v.z - __bfloat162float(h2));
    bf16 l3 = __float2bfloat16(v.w - __bfloat162float(h3));
    uint32_t hp0 = (uint32_t)__bfloat16_as_ushort(h0) | ((uint32_t)__bfloat16_as_ushort(h1) << 16);
    uint32_t hp1 = (uint32_t)__bfloat16_as_ushort(h2) | ((uint32_t)__bfloat16_as_ushort(h3) << 16);
    uint32_t lp0 = (uint32_t)__bfloat16_as_ushort(l0) | ((uint32_t)__bfloat16_as_ushort(l1) << 16);
    uint32_t lp1 = (uint32_t)__bfloat16_as_ushort(l2) | ((uint32_t)__bfloat16_as_ushort(l3) << 16);
    ((uint2*)hi)[i] = make_uint2(hp0, hp1);
    ((uint2*)lo)[i] = make_uint2(lp0, lp1);
}

// ---------------------------------------------------------------------------
// Embedding (fp32 residual stream)
// ---------------------------------------------------------------------------
__global__ void embed_kernel(const int* __restrict__ idx,
                             const float* __restrict__ tok,
                             const float* __restrict__ pos,
                             float* __restrict__ x) {
    int row = blockIdx.x;
    int t = row % T_;
    int id = idx[row];
    const float* tr = tok + (size_t)id * E_;
    const float* pr = pos + (size_t)t * E_;
    float* xr = x + (size_t)row * E_;
    for (int i = threadIdx.x; i < E_; i += blockDim.x)
        xr[i] = tr[i] + pr[i];
}

// ---------------------------------------------------------------------------
// LayerNorm -> (hi, lo) bf16 output
// ---------------------------------------------------------------------------
__global__ void lnorm_split_kernel(const float* __restrict__ x,
                                   const float* __restrict__ s,
                                   const float* __restrict__ b,
                                   bf16* __restrict__ oh,
                                   bf16* __restrict__ ol) {
    int row = blockIdx.x;
    const float* xr = x + (size_t)row * E_;
    __shared__ float red[256];
    int tid = threadIdx.x;

    float sum = 0.f;
    for (int i = tid; i < E_; i += 256) sum += xr[i];
    red[tid] = sum;
    __syncthreads();
    for (int off = 128; off > 0; off >>= 1) {
        if (tid < off) red[tid] += red[tid + off];
        __syncthreads();
    }
    float mu = red[0] * (1.0f / E_);
    __syncthreads();

    float vs = 0.f;
    for (int i = tid; i < E_; i += 256) { float d = xr[i] - mu; vs += d * d; }
    red[tid] = vs;
    __syncthreads();
    for (int off = 128; off > 0; off >>= 1) {
        if (tid < off) red[tid] += red[tid + off];
        __syncthreads();
    }
    float inv = rsqrtf(red[0] * (1.0f / E_) + 1e-5f);

    for (int i = tid; i < E_; i += 256) {
        float v = (xr[i] - mu) * inv * s[i] + b[i];
        split_store(v, &oh[(size_t)row * E_ + i], &ol[(size_t)row * E_ + i]);
    }
}

// ---------------------------------------------------------------------------
// Flash attention (fp32, smem-tiled, online softmax).
// Grid: (qt=T/128, h, b). Block: 256 threads = 16x16.
//   Thread (ty,tx) owns q rows ty*8..+8 and (scores) k cols tx*4..+4,
//   and (output) d cols tx*4..+4. O accumulators 8x4 fp32 in registers.
// SMEM: Qt[64][132] (d-major), Kt[64][68] (d-major), Vt[64][68] (k-major),
//       Ps[128][68], m/l/alpha[128]  -> ~105 KB dynamic.
// Output y written directly as bf16 hi/lo split.
// ---------------------------------------------------------------------------
#define FA_SMEM_FLOATS (64*132 + 64*68 + 64*68 + 128*68 + 3*128)
#define FA_SMEM_BYTES  (FA_SMEM_FLOATS * 4)

__global__ void __launch_bounds__(256, 1)
flash_attn_kernel(const float* __restrict__ qkv,
                  bf16* __restrict__ yh, bf16* __restrict__ yl) {
    extern __shared__ float fs[];
    float* Qt = fs;                    // [64][132]
    float* Kt = Qt + 64 * 132;         // [64][68]
    float* Vt = Kt + 64 * 68;          // [64][68]
    float* Ps = Vt + 64 * 68;          // [128][68]
    float* ms = Ps + 128 * 68;         // [128]
    float* ls = ms + 128;              // [128]
    float* as_ = ls + 128;             // [128]

    const int qt = blockIdx.x, h = blockIdx.y, b = blockIdx.z;
    const int tid = threadIdx.x;
    const int tx = tid & 15, ty = tid >> 4;
    const int q0 = qt * 128;

    const float* qbase = qkv + (size_t)b * T_ * QKV3 + h * D_;
    const float* kbase = qbase + E_;
    const float* vbase = qbase + 2 * E_;

    // Load Q tile transposed: Qt[d][q]
    {
        int qr = tid >> 1;
        int j0 = (tid & 1) * 8;
        const float4* src = (const float4*)(qbase + (size_t)(q0 + qr) * QKV3);
        #pragma unroll
        for (int j = 0; j < 8; j++) {
            float4 v = src[j0 + j];
            int d = (j0 + j) * 4;
            Qt[(d + 0) * 132 + qr] = v.x;
            Qt[(d + 1) * 132 + qr] = v.y;
            Qt[(d + 2) * 132 + qr] = v.z;
            Qt[(d + 3) * 132 + qr] = v.w;
        }
    }
    if (tid < 128) { ms[tid] = -1e30f; ls[tid] = 0.f; }

    float O[8][4] = {};
    const int ntiles = 2 * qt + 2;

    for (int kt = 0; kt < ntiles; kt++) {
        __syncthreads();   // previous iter done with Kt/Vt/Ps (and Qt loaded)
        // Load K tile (transposed -> Kt[d][k]) and V tile (Vt[k][d])
        {
            int kr = tid >> 2;            // 0..63
            int j0 = (tid & 3) * 4;       // 4 float4 quads per thread
            const float4* ksrc = (const float4*)(kbase + (size_t)(kt * 64 + kr) * QKV3);
            const float4* vsrc = (const float4*)(vbase + (size_t)(kt * 64 + kr) * QKV3);
            #pragma unroll
            for (int j = 0; j < 4; j++) {
                float4 kv = ksrc[j0 + j];
                int d = (j0 + j) * 4;
                Kt[(d + 0) * 68 + kr] = kv.x;
                Kt[(d + 1) * 68 + kr] = kv.y;
                Kt[(d + 2) * 68 + kr] = kv.z;
                Kt[(d + 3) * 68 + kr] = kv.w;
                float4 vv = vsrc[j0 + j];
                *(float4*)&Vt[kr * 68 + d] = vv;
            }
        }
        __syncthreads();

        // Scores: s[i][j] = sum_d Q[q0r+i][d] * K[k0c+j][d]
        float s[8][4] = {};
        #pragma unroll 4
        for (int d = 0; d < 64; d++) {
            float4 qa = *(const float4*)&Qt[d * 132 + ty * 8];
            float4 qb = *(const float4*)&Qt[d * 132 + ty * 8 + 4];
            float4 kv = *(const float4*)&Kt[d * 68 + tx * 4];
            float qv[8] = {qa.x, qa.y, qa.z, qa.w, qb.x, qb.y, qb.z, qb.w};
            float kk[4] = {kv.x, kv.y, kv.z, kv.w};
            #pragma unroll
            for (int i = 0; i < 8; i++)
                #pragma unroll
                for (int j = 0; j < 4; j++)
                    s[i][j] += qv[i] * kk[j];
        }
        #pragma unroll
        for (int i = 0; i < 8; i++)
            #pragma unroll
            for (int j = 0; j < 4; j++)
                Ps[(ty * 8 + i) * 68 + tx * 4 + j] = s[i][j];
        __syncthreads();

        // Online softmax update (one thread per query)
        if (tid < 128) {
            const int qg = q0 + tid;
            const int kg0 = kt * 64;
            int kvalid = qg - kg0 + 1;
            kvalid = kvalid < 0 ? 0 : (kvalid > 64 ? 64 : kvalid);
            float m_old = ms[tid];
            float mx = m_old;
            float* prow = &Ps[tid * 68];
            for (int k = 0; k < kvalid; k++)
                mx = fmaxf(mx, prow[k] * 0.125f);
            float alpha = __expf(m_old - mx);
            float sum = 0.f;
            for (int k = 0; k < 64; k++) {
                float p = (k < kvalid) ? __expf(prow[k] * 0.125f - mx) : 0.f;
                prow[k] = p;
                sum += p;
            }
            ls[tid] = ls[tid] * alpha + sum;
            ms[tid] = mx;
            as_[tid] = alpha;
        }
        __syncthreads();

        // O = O * alpha + P @ V
        float al[8];
        #pragma unroll
        for (int i = 0; i < 8; i++) al[i] = as_[ty * 8 + i];
        #pragma unroll
        for (int i = 0; i < 8; i++)
            #pragma unroll
            for (int j = 0; j < 4; j++) O[i][j] *= al[i];
        #pragma unroll 4
        for (int k = 0; k < 64; k++) {
            float4 vv = *(const float4*)&Vt[k * 68 + tx * 4];
            float pv[8];
            #pragma unroll
            for (int i = 0; i < 8; i++) pv[i] = Ps[(ty * 8 + i) * 68 + k];
            #pragma unroll
            for (int i = 0; i < 8; i++) {
                O[i][0] += pv[i] * vv.x;
                O[i][1] += pv[i] * vv.y;
                O[i][2] += pv[i] * vv.z;
                O[i][3] += pv[i] * vv.w;
            }
        }
    }

    // Epilogue: divide by l, split-store to bf16 hi/lo
    #pragma unroll
    for (int i = 0; i < 8; i++) {
        int q = ty * 8 + i;
        float invl = 1.0f / ls[q];
        size_t off = (size_t)(b * T_ + q0 + q) * E_ + h * D_ + tx * 4;
        #pragma unroll
        for (int j = 0; j < 4; j++)
            split_store(O[i][j] * invl, &yh[off + j], &yl[off + j]);
    }
}

// ---------------------------------------------------------------------------
// HMMA bf16x3 GEMM: C[M,N] = A[M,K] @ W[N,K]^T  (unchanged from R3)
// ---------------------------------------------------------------------------
#define GEMM_SMEM_BYTES (2 * 4 * 128 * 128)

__device__ __forceinline__ void load_row8(uint32_t smem_tile,
                                          const bf16* __restrict__ g,
                                          int row0, int K, int k0, int r) {
    const char* gp = (const char*)(g + (size_t)(row0 + r) * K + k0);
    uint32_t rb = (uint32_t)r * 128;
    #pragma unroll
    for (int j = 0; j < 8; j++)
        cp_async16(smem_tile + SWZ128(rb + j * 16), gp + j * 16);
}

template<bool GELU, bool RES, bool OUT32>
__global__ void __launch_bounds__(256, 1)
gemm_hmma_kernel(const bf16* __restrict__ Ahi, const bf16* __restrict__ Alo,
                 const bf16* __restrict__ Bhi, const bf16* __restrict__ Blo,
                 const float* __restrict__ R, float* __restrict__ Cf,
                 bf16* __restrict__ Chi, bf16* __restrict__ Clo,
                 int N, int K) {
    extern __shared__ char smem[];
    const uint32_t sb = smem_u32(smem);

    const int tid = threadIdx.x;
    const int lane = tid & 31;
    const int wid = tid >> 5;
    const int wm = (wid >> 2) * 64;
    const int wn = (wid & 3) * 32;
    const int m0 = blockIdx.y * 128;
    const int n0 = blockIdx.x * 128;
    const int nchunks = K >> 6;

    const int lr = tid & 127;
    const int lt = tid >> 7;
    const bf16* Ag = lt ? Alo : Ahi;
    const bf16* Bg = lt ? Blo : Bhi;
    const uint32_t aoff = (uint32_t)lt * 16384;
    const uint32_t boff = 32768 + (uint32_t)lt * 16384;

    float acc[4][4][4];
    #pragma unroll
    for (int i = 0; i < 4; i++)
        #pragma unroll
        for (int j = 0; j < 4; j++)
            #pragma unroll
            for (int q = 0; q < 4; q++) acc[i][j][q] = 0.f;

    load_row8(sb + aoff, Ag, m0, K, 0, lr);
    load_row8(sb + boff, Bg, n0, K, 0, lr);
    cp_commit();

    const uint32_t a_row = wm + (lane & 15);
    const uint32_t a_cb  = (uint32_t)((lane >> 4) << 4);
    const uint32_t b_cb  = (uint32_t)(((lane >> 3) & 1) << 4);

    for (int c = 0; c < nchunks; c++) {
        const uint32_t st = sb + (uint32_t)(c & 1) * 65536;

        cp_wait<0>();
        __syncthreads();

        if (c + 1 < nchunks) {
            const uint32_t sn = sb + (uint32_t)((c + 1) & 1) * 65536;
            load_row8(sn + aoff, Ag, m0, K, (c + 1) << 6, lr);
            load_row8(sn + boff, Bg, n0, K, (c + 1) << 6, lr);
            cp_commit();
        }

        const uint32_t aAh = st, aAl = st + 16384;
        const uint32_t aBh = st + 32768, aBl = st + 49152;

        #pragma unroll
        for (int ks = 0; ks < 4; ks++) {
            const uint32_t kb = (uint32_t)ks * 32;
            uint32_t ah[4][4], al[4][4], bh[4][2], bl[4][2];
            #pragma unroll
            for (int mi = 0; mi < 4; mi++) {
                uint32_t off = SWZ128((a_row + mi * 16) * 128 + kb + a_cb);
                ldsm_x4(ah[mi], aAh + off);
                ldsm_x4(al[mi], aAl + off);
            }
            #pragma unroll
            for (int ni = 0; ni < 4; ni++) {
                uint32_t off = SWZ128((wn + ni * 8 + (lane & 7)) * 128 + kb + b_cb);
                ldsm_x2(bh[ni], aBh + off);
                ldsm_x2(bl[ni], aBl + off);
            }
            #pragma unroll
            for (int mi = 0; mi < 4; mi++)
                #pragma unroll
                for (int ni = 0; ni < 4; ni++) {
                    mma16816(acc[mi][ni], ah[mi], bh[ni]);
                    mma16816(acc[mi][ni], ah[mi], bl[ni]);
                    mma16816(acc[mi][ni], al[mi], bh[ni]);
                }
        }
        __syncthreads();
    }

    const int er = lane >> 2;
    const int ec = (lane & 3) * 2;

    #pragma unroll
    for (int mi = 0; mi < 4; mi++) {
        #pragma unroll
        for (int ni = 0; ni < 4; ni++) {
            const int row = m0 + wm + mi * 16 + er;
            const int col = n0 + wn + ni * 8 + ec;
            float v0 = acc[mi][ni][0], v1 = acc[mi][ni][1];
            float v2 = acc[mi][ni][2], v3 = acc[mi][ni][3];
            if (RES) {
                float2 r0 = *(const float2*)(R + (size_t)row * N + col);
                float2 r1 = *(const float2*)(R + (size_t)(row + 8) * N + col);
                v0 += r0.x; v1 += r0.y; v2 += r1.x; v3 += r1.y;
            }
            if (GELU) {
                v0 = 0.5f * v0 * (1.0f + erff(v0 * 0.70710678118654752f));
                v1 = 0.5f * v1 * (1.0f + erff(v1 * 0.70710678118654752f));
                v2 = 0.5f * v2 * (1.0f + erff(v2 * 0.70710678118654752f));
                v3 = 0.5f * v3 * (1.0f + erff(v3 * 0.70710678118654752f));
            }
            if (OUT32) {
                *(float2*)(Cf + (size_t)row * N + col) = make_float2(v0, v1);
                *(float2*)(Cf + (size_t)(row + 8) * N + col) = make_float2(v2, v3);
            } else {
                bf16 h0 = __float2bfloat16(v0), h1 = __float2bfloat16(v1);
                bf16 h2 = __float2bfloat16(v2), h3 = __float2bfloat16(v3);
                bf16 l0 = __float2bfloat16(v0 - __bfloat162float(h0));
                bf16 l1 = __float2bfloat16(v1 - __bfloat162float(h1));
                bf16 l2 = __float2bfloat16(v2 - __bfloat162float(h2));
                bf16 l3 = __float2bfloat16(v3 - __bfloat162float(h3));
                *(uint32_t*)(Chi + (size_t)row * N + col) =
                    (uint32_t)__bfloat16_as_ushort(h0) | ((uint32_t)__bfloat16_as_ushort(h1) << 16);
                *(uint32_t*)(Chi + (size_t)(row + 8) * N + col) =
                    (uint32_t)__bfloat16_as_ushort(h2) | ((uint32_t)__bfloat16_as_ushort(h3) << 16);
                *(uint32_t*)(Clo + (size_t)row * N + col) =
                    (uint32_t)__bfloat16_as_ushort(l0) | ((uint32_t)__bfloat16_as_ushort(l1) << 16);
                *(uint32_t*)(Clo + (size_t)(row + 8) * N + col) =
                    (uint32_t)__bfloat16_as_ushort(l2) | ((uint32_t)__bfloat16_as_ushort(l3) << 16);
            }
        }
    }
}

// ---------------------------------------------------------------------------
// Launch
// ---------------------------------------------------------------------------
extern "C" void kernel_launch(void* const* d_in, const int* in_sizes, int n_in,
                              void* d_out, int out_size) {
    const int*   idx    = (const int*)  d_in[0];
    const float* tok    = (const float*)d_in[1];
    const float* pos    = (const float*)d_in[2];
    const float* qkv_w  = (const float*)d_in[3];
    const float* proj_w = (const float*)d_in[4];
    const float* fc_w   = (const float*)d_in[5];
    const float* fcp_w  = (const float*)d_in[6];
    const float* ln1s   = (const float*)d_in[7];
    const float* ln1b   = (const float*)d_in[8];
    const float* ln2s   = (const float*)d_in[9];
    const float* ln2b   = (const float*)d_in[10];
    const float* lnfs   = (const float*)d_in[11];
    const float* lnfb   = (const float*)d_in[12];
    float* out = (float*)d_out;

    float *x, *qkv;
    bf16 *b1h, *b1l, *b2h, *b2l;
    bf16 *wqkvh, *wqkvl, *wprojh, *wprojl, *wfch, *wfcl, *wfcph, *wfcpl, *tokh, *tokl;
    cudaGetSymbolAddress((void**)&x,     g_x);
    cudaGetSymbolAddress((void**)&qkv,   g_qkv);
    cudaGetSymbolAddress((void**)&b1h,   g_b1h);
    cudaGetSymbolAddress((void**)&b1l,   g_b1l);
    cudaGetSymbolAddress((void**)&b2h,   g_b2h);
    cudaGetSymbolAddress((void**)&b2l,   g_b2l);
    cudaGetSymbolAddress((void**)&wqkvh, g_wqkv_h);
    cudaGetSymbolAddress((void**)&wqkvl, g_wqkv_l);
    cudaGetSymbolAddress((void**)&wprojh,g_wproj_h);
    cudaGetSymbolAddress((void**)&wprojl,g_wproj_l);
    cudaGetSymbolAddress((void**)&wfch,  g_wfc_h);
    cudaGetSymbolAddress((void**)&wfcl,  g_wfc_l);
    cudaGetSymbolAddress((void**)&wfcph, g_wfcp_h);
    cudaGetSymbolAddress((void**)&wfcpl, g_wfcp_l);
    cudaGetSymbolAddress((void**)&tokh,  g_tok_h);
    cudaGetSymbolAddress((void**)&tokl,  g_tok_l);

    cudaFuncSetAttribute(gemm_hmma_kernel<false, false, true>,
                         cudaFuncAttributeMaxDynamicSharedMemorySize, GEMM_SMEM_BYTES);
    cudaFuncSetAttribute(gemm_hmma_kernel<false, true, true>,
                         cudaFuncAttributeMaxDynamicSharedMemorySize, GEMM_SMEM_BYTES);
    cudaFuncSetAttribute(gemm_hmma_kernel<true, false, false>,
                         cudaFuncAttributeMaxDynamicSharedMemorySize, GEMM_SMEM_BYTES);
    cudaFuncSetAttribute(flash_attn_kernel,
                         cudaFuncAttributeMaxDynamicSharedMemorySize, FA_SMEM_BYTES);

    // weight splits (fp32 -> bf16 hi/lo)
    {
        int n4;
        n4 = L_ * QKV3 * E_ / 4;
        split_kernel<<<(n4 + 255) / 256, 256>>>(qkv_w, wqkvh, wqkvl, n4);
        n4 = L_ * E_ * E_ / 4;
        split_kernel<<<(n4 + 255) / 256, 256>>>(proj_w, wprojh, wprojl, n4);
        n4 = L_ * FF_ * E_ / 4;
        split_kernel<<<(n4 + 255) / 256, 256>>>(fc_w, wfch, wfcl, n4);
        n4 = L_ * E_ * FF_ / 4;
        split_kernel<<<(n4 + 255) / 256, 256>>>(fcp_w, wfcph, wfcpl, n4);
        n4 = V_ * E_ / 4;
        split_kernel<<<(n4 + 255) / 256, 256>>>(tok, tokh, tokl, n4);
    }

    embed_kernel<<<M_, 256>>>(idx, tok, pos, x);

    for (int l = 0; l < L_; l++) {
        lnorm_split_kernel<<<M_, 256>>>(x, ln1s + (size_t)l * E_, ln1b + (size_t)l * E_, b1h, b1l);
        gemm_hmma_kernel<false, false, true><<<dim3(QKV3 / 128, M_ / 128), 256, GEMM_SMEM_BYTES>>>(
            b1h, b1l, wqkvh + (size_t)l * QKV3 * E_, wqkvl + (size_t)l * QKV3 * E_,
            nullptr, qkv, nullptr, nullptr, QKV3, E_);
        flash_attn_kernel<<<dim3(T_ / 128, H_, B_), 256, FA_SMEM_BYTES>>>(qkv, b1h, b1l);
        gemm_hmma_kernel<false, true, true><<<dim3(E_ / 128, M_ / 128), 256, GEMM_SMEM_BYTES>>>(
            b1h, b1l, wprojh + (size_t)l * E_ * E_, wprojl + (size_t)l * E_ * E_,
            x, x, nullptr, nullptr, E_, E_);
        lnorm_split_kernel<<<M_, 256>>>(x, ln2s + (size_t)l * E_, ln2b + (size_t)l * E_, b1h, b1l);
        gemm_hmma_kernel<true, false, false><<<dim3(FF_ / 128, M_ / 128), 256, GEMM_SMEM_BYTES>>>(
            b1h, b1l, wfch + (size_t)l * FF_ * E_, wfcl + (size_t)l * FF_ * E_,
            nullptr, nullptr, b2h, b2l, FF_, E_);
        gemm_hmma_kernel<false, true, true><<<dim3(E_ / 128, M_ / 128), 256, GEMM_SMEM_BYTES>>>(
            b2h, b2l, wfcph + (size_t)l * E_ * FF_, wfcpl + (size_t)l * E_ * FF_,
            x, x, nullptr, nullptr, E_, FF_);
    }

    lnorm_split_kernel<<<M_, 256>>>(x, lnfs, lnfb, b1h, b1l);
    gemm_hmma_kernel<false, false, true><<<dim3(V_ / 128, M_ / 128), 256, GEMM_SMEM_BYTES>>>(
        b1h, b1l, tokh, tokl, nullptr, out, nullptr, nullptr, V_, E_);
}

// round 5
// speedup vs baseline: 4.8201x; 1.0108x over previous
#include <cuda_runtime.h>
#include <cuda_bf16.h>
#include <math.h>
#include <stdint.h>

// Problem constants
#define V_   32000
#define E_   1024
#define L_   8
#define H_   16
#define B_   2
#define T_   1024
#define D_   64
#define M_   (B_ * T_)      // 2048 rows
#define FF_  (4 * E_)       // 4096
#define QKV3 (3 * E_)       // 3072

typedef __nv_bfloat16 bf16;

// ---------------------------------------------------------------------------
// Scratch (device globals — no allocation allowed in kernel_launch)
// ---------------------------------------------------------------------------
__device__ float g_x[M_ * E_];          // residual stream (fp32)
__device__ float g_qkv[M_ * QKV3];      // fused QKV (fp32, for attention)
__device__ bf16  g_b1h[M_ * E_];        // activation buf1 hi
__device__ bf16  g_b1l[M_ * E_];        // activation buf1 lo
__device__ bf16  g_b2h[M_ * FF_];       // activation buf2 hi (MLP hidden)
__device__ bf16  g_b2l[M_ * FF_];       // activation buf2 lo
// bf16 split weights
__device__ bf16  g_wqkv_h[L_ * QKV3 * E_];
__device__ bf16  g_wqkv_l[L_ * QKV3 * E_];
__device__ bf16  g_wproj_h[L_ * E_ * E_];
__device__ bf16  g_wproj_l[L_ * E_ * E_];
__device__ bf16  g_wfc_h[L_ * FF_ * E_];
__device__ bf16  g_wfc_l[L_ * FF_ * E_];
__device__ bf16  g_wfcp_h[L_ * E_ * FF_];
__device__ bf16  g_wfcp_l[L_ * E_ * FF_];
__device__ bf16  g_tok_h[V_ * E_];
__device__ bf16  g_tok_l[V_ * E_];

// ---------------------------------------------------------------------------
// PTX helpers (base-target features only: cp.async, ldmatrix, mma.sync)
// ---------------------------------------------------------------------------
__device__ __forceinline__ uint32_t smem_u32(const void* p) {
    uint32_t a;
    asm("{ .reg .u64 t; cvta.to.shared.u64 t, %1; cvt.u32.u64 %0, t; }"
        : "=r"(a) : "l"(p));
    return a;
}

#define SWZ128(o) ((o) ^ (((o) >> 3) & 0x70))

__device__ __forceinline__ void cp_async16(uint32_t dst, const void* src) {
    asm volatile("cp.async.cg.shared.global [%0], [%1], 16;\n"
                 :: "r"(dst), "l"(src) : "memory");
}
__device__ __forceinline__ void cp_commit() {
    asm volatile("cp.async.commit_group;\n" ::: "memory");
}
template <int N>
__device__ __forceinline__ void cp_wait() {
    asm volatile("cp.async.wait_group %0;\n" :: "n"(N) : "memory");
}
__device__ __forceinline__ void ldsm_x4(uint32_t* r, uint32_t addr) {
    asm volatile("ldmatrix.sync.aligned.m8n8.x4.shared.b16 {%0,%1,%2,%3}, [%4];"
                 : "=r"(r[0]), "=r"(r[1]), "=r"(r[2]), "=r"(r[3]) : "r"(addr));
}
__device__ __forceinline__ void ldsm_x2(uint32_t* r, uint32_t addr) {
    asm volatile("ldmatrix.sync.aligned.m8n8.x2.shared.b16 {%0,%1}, [%2];"
                 : "=r"(r[0]), "=r"(r[1]) : "r"(addr));
}
__device__ __forceinline__ void mma16816(float* d, const uint32_t* a,
                                         const uint32_t* b) {
    asm volatile(
        "mma.sync.aligned.m16n8k16.row.col.f32.bf16.bf16.f32 "
        "{%0,%1,%2,%3}, {%4,%5,%6,%7}, {%8,%9}, {%0,%1,%2,%3};"
        : "+f"(d[0]), "+f"(d[1]), "+f"(d[2]), "+f"(d[3])
        : "r"(a[0]), "r"(a[1]), "r"(a[2]), "r"(a[3]), "r"(b[0]), "r"(b[1]));
}

__device__ __forceinline__ void split_store(float v, bf16* hp, bf16* lp) {
    bf16 h = __float2bfloat16(v);
    *hp = h;
    *lp = __float2bfloat16(v - __bfloat162float(h));
}

// ---------------------------------------------------------------------------
// Weight split: fp32 -> (hi, lo) bf16, float4 granularity
// ---------------------------------------------------------------------------
__global__ void split_kernel(const float* __restrict__ x,
                             bf16* __restrict__ hi, bf16* __restrict__ lo,
                             int n4) {
    int i = blockIdx.x * blockDim.x + threadIdx.x;
    if (i >= n4) return;
    float4 v = ((const float4*)x)[i];
    bf16 h0 = __float2bfloat16(v.x), h1 = __float2bfloat16(v.y);
    bf16 h2 = __float2bfloat16(v.z), h3 = __float2bfloat16(v.w);
    bf16 l0 = __float2bfloat16(v.x - __bfloat162float(h0));
    bf16 l1 = __float2bfloat16(v.y - __bfloat162float(h1));
    bf16 l2 = __float2bfloat16(v.z - __bfloat162float(h2));
    bf16 l3 = __float2bfloat16(v.w - __bfloat162float(h3));
    uint32_t hp0 = (uint32_t)__bfloat16_as_ushort(h0) | ((uint32_t)__bfloat16_as_ushort(h1) << 16);
    uint32_t hp1 = (uint32_t)__bfloat16_as_ushort(h2) | ((uint32_t)__bfloat16_as_ushort(h3) << 16);
    uint32_t lp0 = (uint32_t)__bfloat16_as_ushort(l0) | ((uint32_t)__bfloat16_as_ushort(l1) << 16);
    uint32_t lp1 = (uint32_t)__bfloat16_as_ushort(l2) | ((uint32_t)__bfloat16_as_ushort(l3) << 16);
    ((uint2*)hi)[i] = make_uint2(hp0, hp1);
    ((uint2*)lo)[i] = make_uint2(lp0, lp1);
}

// ---------------------------------------------------------------------------
// Embedding (fp32 residual stream)
// ---------------------------------------------------------------------------
__global__ void embed_kernel(const int* __restrict__ idx,
                             const float* __restrict__ tok,
                             const float* __restrict__ pos,
                             float* __restrict__ x) {
    int row = blockIdx.x;
    int t = row % T_;
    int id = idx[row];
    const float* tr = tok + (size_t)id * E_;
    const float* pr = pos + (size_t)t * E_;
    float* xr = x + (size_t)row * E_;
    for (int i = threadIdx.x; i < E_; i += blockDim.x)
        xr[i] = tr[i] + pr[i];
}

// ---------------------------------------------------------------------------
// LayerNorm -> (hi, lo) bf16 output
// ---------------------------------------------------------------------------
__global__ void lnorm_split_kernel(const float* __restrict__ x,
                                   const float* __restrict__ s,
                                   const float* __restrict__ b,
                                   bf16* __restrict__ oh,
                                   bf16* __restrict__ ol) {
    int row = blockIdx.x;
    const float* xr = x + (size_t)row * E_;
    __shared__ float red[256];
    int tid = threadIdx.x;

    float sum = 0.f;
    for (int i = tid; i < E_; i += 256) sum += xr[i];
    red[tid] = sum;
    __syncthreads();
    for (int off = 128; off > 0; off >>= 1) {
        if (tid < off) red[tid] += red[tid + off];
        __syncthreads();
    }
    float mu = red[0] * (1.0f / E_);
    __syncthreads();

    float vs = 0.f;
    for (int i = tid; i < E_; i += 256) { float d = xr[i] - mu; vs += d * d; }
    red[tid] = vs;
    __syncthreads();
    for (int off = 128; off > 0; off >>= 1) {
        if (tid < off) red[tid] += red[tid + off];
        __syncthreads();
    }
    float inv = rsqrtf(red[0] * (1.0f / E_) + 1e-5f);

    for (int i = tid; i < E_; i += 256) {
        float v = (xr[i] - mu) * inv * s[i] + b[i];
        split_store(v, &oh[(size_t)row * E_ + i], &ol[(size_t)row * E_ + i]);
    }
}

// ---------------------------------------------------------------------------
// Flash attention (fp32, smem-tiled, online softmax with warp-parallel
// softmax: row max/sum via shfl over the 16 lanes owning each row, exp in
// registers, alpha kept in registers for the P@V rescale).
// Grid: (qt=T/128, h, b). Block: 256 threads = 16x16.
// ---------------------------------------------------------------------------
#define FA_SMEM_FLOATS (64*132 + 64*68 + 64*68 + 128*68 + 2*128)
#define FA_SMEM_BYTES  (FA_SMEM_FLOATS * 4)

__global__ void __launch_bounds__(256, 1)
flash_attn_kernel(const float* __restrict__ qkv,
                  bf16* __restrict__ yh, bf16* __restrict__ yl) {
    extern __shared__ float fs[];
    float* Qt = fs;                    // [64][132] d-major Q
    float* Kt = Qt + 64 * 132;         // [64][68]  d-major K
    float* Vt = Kt + 64 * 68;          // [64][68]  k-major V
    float* Ps = Vt + 64 * 68;          // [128][68] probabilities
    float* ms = Ps + 128 * 68;         // [128] running max
    float* ls = ms + 128;              // [128] running sum

    const int qt = blockIdx.x, h = blockIdx.y, b = blockIdx.z;
    const int tid = threadIdx.x;
    const int tx = tid & 15, ty = tid >> 4;
    const int q0 = qt * 128;

    const float* qbase = qkv + (size_t)b * T_ * QKV3 + h * D_;
    const float* kbase = qbase + E_;
    const float* vbase = qbase + 2 * E_;

    // Load Q tile transposed: Qt[d][q]
    {
        int qr = tid >> 1;
        int j0 = (tid & 1) * 8;
        const float4* src = (const float4*)(qbase + (size_t)(q0 + qr) * QKV3);
        #pragma unroll
        for (int j = 0; j < 8; j++) {
            float4 v = src[j0 + j];
            int d = (j0 + j) * 4;
            Qt[(d + 0) * 132 + qr] = v.x;
            Qt[(d + 1) * 132 + qr] = v.y;
            Qt[(d + 2) * 132 + qr] = v.z;
            Qt[(d + 3) * 132 + qr] = v.w;
        }
    }
    if (tid < 128) { ms[tid] = -1e30f; ls[tid] = 0.f; }

    float O[8][4] = {};
    const int ntiles = 2 * qt + 2;
    const float scale = 0.125f;   // 1/sqrt(64)

    for (int kt = 0; kt < ntiles; kt++) {
        __syncthreads();   // previous iter done with Kt/Vt/Ps
        // Load K tile (transposed -> Kt[d][k]) and V tile (Vt[k][d])
        {
            int kr = tid >> 2;            // 0..63
            int j0 = (tid & 3) * 4;
            const float4* ksrc = (const float4*)(kbase + (size_t)(kt * 64 + kr) * QKV3);
            const float4* vsrc = (const float4*)(vbase + (size_t)(kt * 64 + kr) * QKV3);
            #pragma unroll
            for (int j = 0; j < 4; j++) {
                float4 kv = ksrc[j0 + j];
                int d = (j0 + j) * 4;
                Kt[(d + 0) * 68 + kr] = kv.x;
                Kt[(d + 1) * 68 + kr] = kv.y;
                Kt[(d + 2) * 68 + kr] = kv.z;
                Kt[(d + 3) * 68 + kr] = kv.w;
                float4 vv = vsrc[j0 + j];
                *(float4*)&Vt[kr * 68 + d] = vv;
            }
        }
        __syncthreads();

        // Scores: s[i][j] = sum_d Q[q][d] * K[k][d]
        float s[8][4] = {};
        #pragma unroll 4
        for (int d = 0; d < 64; d++) {
            float4 qa = *(const float4*)&Qt[d * 132 + ty * 8];
            float4 qb = *(const float4*)&Qt[d * 132 + ty * 8 + 4];
            float4 kv = *(const float4*)&Kt[d * 68 + tx * 4];
            float qv[8] = {qa.x, qa.y, qa.z, qa.w, qb.x, qb.y, qb.z, qb.w};
            float kk[4] = {kv.x, kv.y, kv.z, kv.w};
            #pragma unroll
            for (int i = 0; i < 8; i++)
                #pragma unroll
                for (int j = 0; j < 4; j++)
                    s[i][j] += qv[i] * kk[j];
        }

        // Warp-parallel online softmax. Row r = ty*8+i owned by the 16 lanes
        // sharing ty (all in one warp). Reductions via shfl_xor 1,2,4,8.
        float alpha[8];
        #pragma unroll
        for (int i = 0; i < 8; i++) {
            const int qg = q0 + ty * 8 + i;
            const int kg0 = kt * 64 + tx * 4;
            float m_old = ms[ty * 8 + i];   // read before shfl sync points
            float mloc = -1e30f;
            #pragma unroll
            for (int j = 0; j < 4; j++) {
                float v = (kg0 + j <= qg) ? s[i][j] * scale : -1e30f;
                s[i][j] = v;
                mloc = fmaxf(mloc, v);
            }
            #pragma unroll
            for (int mk = 1; mk < 16; mk <<= 1)
                mloc = fmaxf(mloc, __shfl_xor_sync(0xffffffffu, mloc, mk));
            float mx = fmaxf(m_old, mloc);
            float psum = 0.f;
            #pragma unroll
            for (int j = 0; j < 4; j++) {
                float p = __expf(s[i][j] - mx);
                s[i][j] = p;
                psum += p;
            }
            #pragma unroll
            for (int mk = 1; mk < 16; mk <<= 1)
                psum += __shfl_xor_sync(0xffffffffu, psum, mk);
            alpha[i] = __expf(m_old - mx);
            if (tx == 0) {   // single writer; readers synced via shfl above /
                             // __syncthreads below
                ls[ty * 8 + i] = ls[ty * 8 + i] * alpha[i] + psum;
                ms[ty * 8 + i] = mx;
            }
            // stage probabilities for the P@V pass (other warps read them)
            #pragma unroll
            for (int j = 0; j < 4; j++)
                Ps[(ty * 8 + i) * 68 + tx * 4 + j] = s[i][j];
        }
        __syncthreads();

        // O = O * alpha + P @ V  (alpha per-row from registers)
        #pragma unroll
        for (int i = 0; i < 8; i++)
            #pragma unroll
            for (int j = 0; j < 4; j++) O[i][j] *= alpha[i];
        #pragma unroll 4
        for (int k = 0; k < 64; k++) {
            float4 vv = *(const float4*)&Vt[k * 68 + tx * 4];
            float pv[8];
            #pragma unroll
            for (int i = 0; i < 8; i++) pv[i] = Ps[(ty * 8 + i) * 68 + k];
            #pragma unroll
            for (int i = 0; i < 8; i++) {
                O[i][0] += pv[i] * vv.x;
                O[i][1] += pv[i] * vv.y;
                O[i][2] += pv[i] * vv.z;
                O[i][3] += pv[i] * vv.w;
            }
        }
    }

    // Epilogue: divide by l, split-store to bf16 hi/lo
    #pragma unroll
    for (int i = 0; i < 8; i++) {
        int q = ty * 8 + i;
        float invl = 1.0f / ls[q];
        size_t off = (size_t)(b * T_ + q0 + q) * E_ + h * D_ + tx * 4;
        #pragma unroll
        for (int j = 0; j < 4; j++)
            split_store(O[i][j] * invl, &yh[off + j], &yl[off + j]);
    }
}

// ---------------------------------------------------------------------------
// HMMA bf16x3 GEMM: C[M,N] = A[M,K] @ W[N,K]^T
//   3-stage cp.async pipeline (192 KB smem), term-major MMA ordering to break
//   same-accumulator RAW chains.
// ---------------------------------------------------------------------------
#define GEMM_STAGE_BYTES 65536
#define GEMM_SMEM_BYTES (3 * GEMM_STAGE_BYTES)

__device__ __forceinline__ void load_row8(uint32_t smem_tile,
                                          const bf16* __restrict__ g,
                                          int row0, int K, int k0, int r) {
    const char* gp = (const char*)(g + (size_t)(row0 + r) * K + k0);
    uint32_t rb = (uint32_t)r * 128;
    #pragma unroll
    for (int j = 0; j < 8; j++)
        cp_async16(smem_tile + SWZ128(rb + j * 16), gp + j * 16);
}

template<bool GELU, bool RES, bool OUT32>
__global__ void __launch_bounds__(256, 1)
gemm_hmma_kernel(const bf16* __restrict__ Ahi, const bf16* __restrict__ Alo,
                 const bf16* __restrict__ Bhi, const bf16* __restrict__ Blo,
                 const float* __restrict__ R, float* __restrict__ Cf,
                 bf16* __restrict__ Chi, bf16* __restrict__ Clo,
                 int N, int K) {
    extern __shared__ char smem[];
    const uint32_t sb = smem_u32(smem);

    const int tid = threadIdx.x;
    const int lane = tid & 31;
    const int wid = tid >> 5;
    const int wm = (wid >> 2) * 64;
    const int wn = (wid & 3) * 32;
    const int m0 = blockIdx.y * 128;
    const int n0 = blockIdx.x * 128;
    const int nchunks = K >> 6;

    const int lr = tid & 127;
    const int lt = tid >> 7;
    const bf16* Ag = lt ? Alo : Ahi;
    const bf16* Bg = lt ? Blo : Bhi;
    const uint32_t aoff = (uint32_t)lt * 16384;
    const uint32_t boff = 32768 + (uint32_t)lt * 16384;

    float acc[4][4][4];
    #pragma unroll
    for (int i = 0; i < 4; i++)
        #pragma unroll
        for (int j = 0; j < 4; j++)
            #pragma unroll
            for (int q = 0; q < 4; q++) acc[i][j][q] = 0.f;

    // preload chunks 0 and 1 into stages 0, 1
    load_row8(sb + aoff, Ag, m0, K, 0, lr);
    load_row8(sb + boff, Bg, n0, K, 0, lr);
    cp_commit();
    if (nchunks > 1) {
        load_row8(sb + GEMM_STAGE_BYTES + aoff, Ag, m0, K, 64, lr);
        load_row8(sb + GEMM_STAGE_BYTES + boff, Bg, n0, K, 64, lr);
        cp_commit();
    }

    const uint32_t a_row = wm + (lane & 15);
    const uint32_t a_cb  = (uint32_t)((lane >> 4) << 4);
    const uint32_t b_cb  = (uint32_t)(((lane >> 3) & 1) << 4);

    for (int c = 0; c < nchunks; c++) {
        const uint32_t st = sb + (uint32_t)(c % 3) * GEMM_STAGE_BYTES;

        if (c + 1 < nchunks) cp_wait<1>();   // chunk c complete, c+1 may fly
        else                 cp_wait<0>();
        __syncthreads();

        if (c + 2 < nchunks) {
            const uint32_t sn = sb + (uint32_t)((c + 2) % 3) * GEMM_STAGE_BYTES;
            load_row8(sn + aoff, Ag, m0, K, (c + 2) << 6, lr);
            load_row8(sn + boff, Bg, n0, K, (c + 2) << 6, lr);
            cp_commit();
        }

        const uint32_t aAh = st, aAl = st + 16384;
        const uint32_t aBh = st + 32768, aBl = st + 49152;

        #pragma unroll
        for (int ks = 0; ks < 4; ks++) {
            const uint32_t kb = (uint32_t)ks * 32;
            uint32_t ah[4][4], al[4][4], bh[4][2], bl[4][2];
            #pragma unroll
            for (int mi = 0; mi < 4; mi++) {
                uint32_t off = SWZ128((a_row + mi * 16) * 128 + kb + a_cb);
                ldsm_x4(ah[mi], aAh + off);
                ldsm_x4(al[mi], aAl + off);
            }
            #pragma unroll
            for (int ni = 0; ni < 4; ni++) {
                uint32_t off = SWZ128((wn + ni * 8 + (lane & 7)) * 128 + kb + b_cb);
                ldsm_x2(bh[ni], aBh + off);
                ldsm_x2(bl[ni], aBl + off);
            }
            // term-major: 16 independent accumulators between same-acc reuse
            #pragma unroll
            for (int mi = 0; mi < 4; mi++)
                #pragma unroll
                for (int ni = 0; ni < 4; ni++)
                    mma16816(acc[mi][ni], ah[mi], bh[ni]);
            #pragma unroll
            for (int mi = 0; mi < 4; mi++)
                #pragma unroll
                for (int ni = 0; ni < 4; ni++)
                    mma16816(acc[mi][ni], ah[mi], bl[ni]);
            #pragma unroll
            for (int mi = 0; mi < 4; mi++)
                #pragma unroll
                for (int ni = 0; ni < 4; ni++)
                    mma16816(acc[mi][ni], al[mi], bh[ni]);
        }
        __syncthreads();   // all warps done reading stage c%3
    }

    const int er = lane >> 2;
    const int ec = (lane & 3) * 2;

    #pragma unroll
    for (int mi = 0; mi < 4; mi++) {
        #pragma unroll
        for (int ni = 0; ni < 4; ni++) {
            const int row = m0 + wm + mi * 16 + er;
            const int col = n0 + wn + ni * 8 + ec;
            float v0 = acc[mi][ni][0], v1 = acc[mi][ni][1];
            float v2 = acc[mi][ni][2], v3 = acc[mi][ni][3];
            if (RES) {
                float2 r0 = *(const float2*)(R + (size_t)row * N + col);
                float2 r1 = *(const float2*)(R + (size_t)(row + 8) * N + col);
                v0 += r0.x; v1 += r0.y; v2 += r1.x; v3 += r1.y;
            }
            if (GELU) {
                v0 = 0.5f * v0 * (1.0f + erff(v0 * 0.70710678118654752f));
                v1 = 0.5f * v1 * (1.0f + erff(v1 * 0.70710678118654752f));
                v2 = 0.5f * v2 * (1.0f + erff(v2 * 0.70710678118654752f));
                v3 = 0.5f * v3 * (1.0f + erff(v3 * 0.70710678118654752f));
            }
            if (OUT32) {
                *(float2*)(Cf + (size_t)row * N + col) = make_float2(v0, v1);
                *(float2*)(Cf + (size_t)(row + 8) * N + col) = make_float2(v2, v3);
            } else {
                bf16 h0 = __float2bfloat16(v0), h1 = __float2bfloat16(v1);
                bf16 h2 = __float2bfloat16(v2), h3 = __float2bfloat16(v3);
                bf16 l0 = __float2bfloat16(v0 - __bfloat162float(h0));
                bf16 l1 = __float2bfloat16(v1 - __bfloat162float(h1));
                bf16 l2 = __float2bfloat16(v2 - __bfloat162float(h2));
                bf16 l3 = __float2bfloat16(v3 - __bfloat162float(h3));
                *(uint32_t*)(Chi + (size_t)row * N + col) =
                    (uint32_t)__bfloat16_as_ushort(h0) | ((uint32_t)__bfloat16_as_ushort(h1) << 16);
                *(uint32_t*)(Chi + (size_t)(row + 8) * N + col) =
                    (uint32_t)__bfloat16_as_ushort(h2) | ((uint32_t)__bfloat16_as_ushort(h3) << 16);
                *(uint32_t*)(Clo + (size_t)row * N + col) =
                    (uint32_t)__bfloat16_as_ushort(l0) | ((uint32_t)__bfloat16_as_ushort(l1) << 16);
                *(uint32_t*)(Clo + (size_t)(row + 8) * N + col) =
                    (uint32_t)__bfloat16_as_ushort(l2) | ((uint32_t)__bfloat16_as_ushort(l3) << 16);
            }
        }
    }
}

// ---------------------------------------------------------------------------
// Launch
// ---------------------------------------------------------------------------
extern "C" void kernel_launch(void* const* d_in, const int* in_sizes, int n_in,
                              void* d_out, int out_size) {
    const int*   idx    = (const int*)  d_in[0];
    const float* tok    = (const float*)d_in[1];
    const float* pos    = (const float*)d_in[2];
    const float* qkv_w  = (const float*)d_in[3];
    const float* proj_w = (const float*)d_in[4];
    const float* fc_w   = (const float*)d_in[5];
    const float* fcp_w  = (const float*)d_in[6];
    const float* ln1s   = (const float*)d_in[7];
    const float* ln1b   = (const float*)d_in[8];
    const float* ln2s   = (const float*)d_in[9];
    const float* ln2b   = (const float*)d_in[10];
    const float* lnfs   = (const float*)d_in[11];
    const float* lnfb   = (const float*)d_in[12];
    float* out = (float*)d_out;

    float *x, *qkv;
    bf16 *b1h, *b1l, *b2h, *b2l;
    bf16 *wqkvh, *wqkvl, *wprojh, *wprojl, *wfch, *wfcl, *wfcph, *wfcpl, *tokh, *tokl;
    cudaGetSymbolAddress((void**)&x,     g_x);
    cudaGetSymbolAddress((void**)&qkv,   g_qkv);
    cudaGetSymbolAddress((void**)&b1h,   g_b1h);
    cudaGetSymbolAddress((void**)&b1l,   g_b1l);
    cudaGetSymbolAddress((void**)&b2h,   g_b2h);
    cudaGetSymbolAddress((void**)&b2l,   g_b2l);
    cudaGetSymbolAddress((void**)&wqkvh, g_wqkv_h);
    cudaGetSymbolAddress((void**)&wqkvl, g_wqkv_l);
    cudaGetSymbolAddress((void**)&wprojh,g_wproj_h);
    cudaGetSymbolAddress((void**)&wprojl,g_wproj_l);
    cudaGetSymbolAddress((void**)&wfch,  g_wfc_h);
    cudaGetSymbolAddress((void**)&wfcl,  g_wfc_l);
    cudaGetSymbolAddress((void**)&wfcph, g_wfcp_h);
    cudaGetSymbolAddress((void**)&wfcpl, g_wfcp_l);
    cudaGetSymbolAddress((void**)&tokh,  g_tok_h);
    cudaGetSymbolAddress((void**)&tokl,  g_tok_l);

    cudaFuncSetAttribute(gemm_hmma_kernel<false, false, true>,
                         cudaFuncAttributeMaxDynamicSharedMemorySize, GEMM_SMEM_BYTES);
    cudaFuncSetAttribute(gemm_hmma_kernel<false, true, true>,
                         cudaFuncAttributeMaxDynamicSharedMemorySize, GEMM_SMEM_BYTES);
    cudaFuncSetAttribute(gemm_hmma_kernel<true, false, false>,
                         cudaFuncAttributeMaxDynamicSharedMemorySize, GEMM_SMEM_BYTES);
    cudaFuncSetAttribute(flash_attn_kernel,
                         cudaFuncAttributeMaxDynamicSharedMemorySize, FA_SMEM_BYTES);

    // weight splits (fp32 -> bf16 hi/lo)
    {
        int n4;
        n4 = L_ * QKV3 * E_ / 4;
        split_kernel<<<(n4 + 255) / 256, 256>>>(qkv_w, wqkvh, wqkvl, n4);
        n4 = L_ * E_ * E_ / 4;
        split_kernel<<<(n4 + 255) / 256, 256>>>(proj_w, wprojh, wprojl, n4);
        n4 = L_ * FF_ * E_ / 4;
        split_kernel<<<(n4 + 255) / 256, 256>>>(fc_w, wfch, wfcl, n4);
        n4 = L_ * E_ * FF_ / 4;
        split_kernel<<<(n4 + 255) / 256, 256>>>(fcp_w, wfcph, wfcpl, n4);
        n4 = V_ * E_ / 4;
        split_kernel<<<(n4 + 255) / 256, 256>>>(tok, tokh, tokl, n4);
    }

    embed_kernel<<<M_, 256>>>(idx, tok, pos, x);

    for (int l = 0; l < L_; l++) {
        lnorm_split_kernel<<<M_, 256>>>(x, ln1s + (size_t)l * E_, ln1b + (size_t)l * E_, b1h, b1l);
        gemm_hmma_kernel<false, false, true><<<dim3(QKV3 / 128, M_ / 128), 256, GEMM_SMEM_BYTES>>>(
            b1h, b1l, wqkvh + (size_t)l * QKV3 * E_, wqkvl + (size_t)l * QKV3 * E_,
            nullptr, qkv, nullptr, nullptr, QKV3, E_);
        flash_attn_kernel<<<dim3(T_ / 128, H_, B_), 256, FA_SMEM_BYTES>>>(qkv, b1h, b1l);
        gemm_hmma_kernel<false, true, true><<<dim3(E_ / 128, M_ / 128), 256, GEMM_SMEM_BYTES>>>(
            b1h, b1l, wprojh + (size_t)l * E_ * E_, wprojl + (size_t)l * E_ * E_,
            x, x, nullptr, nullptr, E_, E_);
        lnorm_split_kernel<<<M_, 256>>>(x, ln2s + (size_t)l * E_, ln2b + (size_t)l * E_, b1h, b1l);
        gemm_hmma_kernel<true, false, false><<<dim3(FF_ / 128, M_ / 128), 256, GEMM_SMEM_BYTES>>>(
            b1h, b1l, wfch + (size_t)l * FF_ * E_, wfcl + (size_t)l * FF_ * E_,
            nullptr, nullptr, b2h, b2l, FF_, E_);
        gemm_hmma_kernel<false, true, true><<<dim3(E_ / 128, M_ / 128), 256, GEMM_SMEM_BYTES>>>(
            b2h, b2l, wfcph + (size_t)l * E_ * FF_, wfcpl + (size_t)l * E_ * FF_,
            x, x, nullptr, nullptr, E_, FF_);
    }

    lnorm_split_kernel<<<M_, 256>>>(x, lnfs, lnfb, b1h, b1l);
    gemm_hmma_kernel<false, false, true><<<dim3(V_ / 128, M_ / 128), 256, GEMM_SMEM_BYTES>>>(
        b1h, b1l, tokh, tokl, nullptr, out, nullptr, nullptr, V_, E_);
}

// round 9
// speedup vs baseline: 6.2114x; 1.2886x over previous
#include <cuda_runtime.h>
#include <cuda_fp16.h>
#include <math.h>
#include <stdint.h>

// Problem constants
#define V_   32000
#define E_   1024
#define L_   8
#define H_   16
#define B_   2
#define T_   1024
#define D_   64
#define M_   (B_ * T_)      // 2048 rows
#define FF_  (4 * E_)       // 4096
#define QKV3 (3 * E_)       // 3072

// ---------------------------------------------------------------------------
// Scratch (device globals — no allocation allowed in kernel_launch)
// ---------------------------------------------------------------------------
__device__ float  g_x[M_ * E_];          // residual stream (fp32)
__device__ float  g_qkv[M_ * QKV3];      // fused QKV (fp32, for attention)
__device__ __half g_b1[M_ * E_];         // activation buf1 (fp16)
__device__ __half g_b2[M_ * FF_];        // activation buf2 (fp16, MLP hidden)
// fp16 split weights (hi + lo)
__device__ __half g_wqkv_h[L_ * QKV3 * E_];
__device__ __half g_wqkv_l[L_ * QKV3 * E_];
__device__ __half g_wproj_h[L_ * E_ * E_];
__device__ __half g_wproj_l[L_ * E_ * E_];
__device__ __half g_wfc_h[L_ * FF_ * E_];
__device__ __half g_wfc_l[L_ * FF_ * E_];
__device__ __half g_wfcp_h[L_ * E_ * FF_];
__device__ __half g_wfcp_l[L_ * E_ * FF_];
__device__ __half g_tok_h[V_ * E_];
__device__ __half g_tok_l[V_ * E_];

// ---------------------------------------------------------------------------
// PTX helpers (base-target features only: cp.async, ldmatrix, mma.sync)
// ---------------------------------------------------------------------------
__device__ __forceinline__ uint32_t smem_u32(const void* p) {
    uint32_t a;
    asm("{ .reg .u64 t; cvta.to.shared.u64 t, %1; cvt.u32.u64 %0, t; }"
        : "=r"(a) : "l"(p));
    return a;
}

#define SWZ128(o) ((o) ^ (((o) >> 3) & 0x70))

__device__ __forceinline__ void cp_async16(uint32_t dst, const void* src) {
    asm volatile("cp.async.cg.shared.global [%0], [%1], 16;\n"
                 :: "r"(dst), "l"(src) : "memory");
}
__device__ __forceinline__ void cp_commit() {
    asm volatile("cp.async.commit_group;\n" ::: "memory");
}
template <int N>
__device__ __forceinline__ void cp_wait() {
    asm volatile("cp.async.wait_group %0;\n" :: "n"(N) : "memory");
}
__device__ __forceinline__ void ldsm_x4(uint32_t* r, uint32_t addr) {
    asm volatile("ldmatrix.sync.aligned.m8n8.x4.shared.b16 {%0,%1,%2,%3}, [%4];"
                 : "=r"(r[0]), "=r"(r[1]), "=r"(r[2]), "=r"(r[3]) : "r"(addr));
}
__device__ __forceinline__ void ldsm_x2(uint32_t* r, uint32_t addr) {
    asm volatile("ldmatrix.sync.aligned.m8n8.x2.shared.b16 {%0,%1}, [%2];"
                 : "=r"(r[0]), "=r"(r[1]) : "r"(addr));
}
__device__ __forceinline__ void mma16816(float* d, const uint32_t* a,
                                         const uint32_t* b) {
    asm volatile(
        "mma.sync.aligned.m16n8k16.row.col.f32.f16.f16.f32 "
        "{%0,%1,%2,%3}, {%4,%5,%6,%7}, {%8,%9}, {%0,%1,%2,%3};"
        : "+f"(d[0]), "+f"(d[1]), "+f"(d[2]), "+f"(d[3])
        : "r"(a[0]), "r"(a[1]), "r"(a[2]), "r"(a[3]), "r"(b[0]), "r"(b[1]));
}

// ---------------------------------------------------------------------------
// Weight split: fp32 -> (hi, lo) fp16, float4 granularity
// ---------------------------------------------------------------------------
__global__ void split_kernel(const float* __restrict__ x,
                             __half* __restrict__ hi, __half* __restrict__ lo,
                             int n4) {
    int i = blockIdx.x * blockDim.x + threadIdx.x;
    if (i >= n4) return;
    float4 v = ((const float4*)x)[i];
    __half h0 = __float2half_rn(v.x), h1 = __float2half_rn(v.y);
    __half h2 = __float2half_rn(v.z), h3 = __float2half_rn(v.w);
    __half l0 = __float2half_rn(v.x - __half2float(h0));
    __half l1 = __float2half_rn(v.y - __half2float(h1));
    __half l2 = __float2half_rn(v.z - __half2float(h2));
    __half l3 = __float2half_rn(v.w - __half2float(h3));
    uint32_t hp0 = (uint32_t)__half_as_ushort(h0) | ((uint32_t)__half_as_ushort(h1) << 16);
    uint32_t hp1 = (uint32_t)__half_as_ushort(h2) | ((uint32_t)__half_as_ushort(h3) << 16);
    uint32_t lp0 = (uint32_t)__half_as_ushort(l0) | ((uint32_t)__half_as_ushort(l1) << 16);
    uint32_t lp1 = (uint32_t)__half_as_ushort(l2) | ((uint32_t)__half_as_ushort(l3) << 16);
    ((uint2*)hi)[i] = make_uint2(hp0, hp1);
    ((uint2*)lo)[i] = make_uint2(lp0, lp1);
}

// ---------------------------------------------------------------------------
// Embedding (fp32 residual stream)
// ---------------------------------------------------------------------------
__global__ void embed_kernel(const int* __restrict__ idx,
                             const float* __restrict__ tok,
                             const float* __restrict__ pos,
                             float* __restrict__ x) {
    int row = blockIdx.x;
    int t = row % T_;
    int id = idx[row];
    const float* tr = tok + (size_t)id * E_;
    const float* pr = pos + (size_t)t * E_;
    float* xr = x + (size_t)row * E_;
    for (int i = threadIdx.x; i < E_; i += blockDim.x)
        xr[i] = tr[i] + pr[i];
}

// ---------------------------------------------------------------------------
// LayerNorm -> fp16 output
// ---------------------------------------------------------------------------
__global__ void lnorm_h_kernel(const float* __restrict__ x,
                               const float* __restrict__ s,
                               const float* __restrict__ b,
                               __half* __restrict__ o) {
    int row = blockIdx.x;
    const float* xr = x + (size_t)row * E_;
    __shared__ float red[256];
    int tid = threadIdx.x;

    float sum = 0.f;
    for (int i = tid; i < E_; i += 256) sum += xr[i];
    red[tid] = sum;
    __syncthreads();
    for (int off = 128; off > 0; off >>= 1) {
        if (tid < off) red[tid] += red[tid + off];
        __syncthreads();
    }
    float mu = red[0] * (1.0f / E_);
    __syncthreads();

    float vs = 0.f;
    for (int i = tid; i < E_; i += 256) { float d = xr[i] - mu; vs += d * d; }
    red[tid] = vs;
    __syncthreads();
    for (int off = 128; off > 0; off >>= 1) {
        if (tid < off) red[tid] += red[tid + off];
        __syncthreads();
    }
    float inv = rsqrtf(red[0] * (1.0f / E_) + 1e-5f);

    for (int i = tid; i < E_; i += 256) {
        float v = (xr[i] - mu) * inv * s[i] + b[i];
        o[(size_t)row * E_ + i] = __float2half_rn(v);
    }
}

// ---------------------------------------------------------------------------
// Flash attention (fp32, smem-tiled, warp-parallel online softmax) -> fp16
// Grid: (qt=T/128, h, b). Block: 256 threads = 16x16.
// ---------------------------------------------------------------------------
#define FA_SMEM_FLOATS (64*132 + 64*68 + 64*68 + 128*68 + 2*128)
#define FA_SMEM_BYTES  (FA_SMEM_FLOATS * 4)

__global__ void __launch_bounds__(256, 1)
flash_attn_kernel(const float* __restrict__ qkv, __half* __restrict__ y) {
    extern __shared__ float fs[];
    float* Qt = fs;                    // [64][132] d-major Q
    float* Kt = Qt + 64 * 132;         // [64][68]  d-major K
    float* Vt = Kt + 64 * 68;          // [64][68]  k-major V
    float* Ps = Vt + 64 * 68;          // [128][68] probabilities
    float* ms = Ps + 128 * 68;         // [128] running max
    float* ls = ms + 128;              // [128] running sum

    const int qt = blockIdx.x, h = blockIdx.y, b = blockIdx.z;
    const int tid = threadIdx.x;
    const int tx = tid & 15, ty = tid >> 4;
    const int q0 = qt * 128;

    const float* qbase = qkv + (size_t)b * T_ * QKV3 + h * D_;
    const float* kbase = qbase + E_;
    const float* vbase = qbase + 2 * E_;

    // Load Q tile transposed: Qt[d][q]
    {
        int qr = tid >> 1;
        int j0 = (tid & 1) * 8;
        const float4* src = (const float4*)(qbase + (size_t)(q0 + qr) * QKV3);
        #pragma unroll
        for (int j = 0; j < 8; j++) {
            float4 v = src[j0 + j];
            int d = (j0 + j) * 4;
            Qt[(d + 0) * 132 + qr] = v.x;
            Qt[(d + 1) * 132 + qr] = v.y;
            Qt[(d + 2) * 132 + qr] = v.z;
            Qt[(d + 3) * 132 + qr] = v.w;
        }
    }
    if (tid < 128) { ms[tid] = -1e30f; ls[tid] = 0.f; }

    float O[8][4] = {};
    const int ntiles = 2 * qt + 2;
    const float scale = 0.125f;   // 1/sqrt(64)

    for (int kt = 0; kt < ntiles; kt++) {
        __syncthreads();
        {
            int kr = tid >> 2;
            int j0 = (tid & 3) * 4;
            const float4* ksrc = (const float4*)(kbase + (size_t)(kt * 64 + kr) * QKV3);
            const float4* vsrc = (const float4*)(vbase + (size_t)(kt * 64 + kr) * QKV3);
            #pragma unroll
            for (int j = 0; j < 4; j++) {
                float4 kv = ksrc[j0 + j];
                int d = (j0 + j) * 4;
                Kt[(d + 0) * 68 + kr] = kv.x;
                Kt[(d + 1) * 68 + kr] = kv.y;
                Kt[(d + 2) * 68 + kr] = kv.z;
                Kt[(d + 3) * 68 + kr] = kv.w;
                float4 vv = vsrc[j0 + j];
                *(float4*)&Vt[kr * 68 + d] = vv;
            }
        }
        __syncthreads();

        // Scores
        float s[8][4] = {};
        #pragma unroll 4
        for (int d = 0; d < 64; d++) {
            float4 qa = *(const float4*)&Qt[d * 132 + ty * 8];
            float4 qb = *(const float4*)&Qt[d * 132 + ty * 8 + 4];
            float4 kv = *(const float4*)&Kt[d * 68 + tx * 4];
            float qv[8] = {qa.x, qa.y, qa.z, qa.w, qb.x, qb.y, qb.z, qb.w};
            float kk[4] = {kv.x, kv.y, kv.z, kv.w};
            #pragma unroll
            for (int i = 0; i < 8; i++)
                #pragma unroll
                for (int j = 0; j < 4; j++)
                    s[i][j] += qv[i] * kk[j];
        }

        // Warp-parallel online softmax
        float alpha[8];
        #pragma unroll
        for (int i = 0; i < 8; i++) {
            const int qg = q0 + ty * 8 + i;
            const int kg0 = kt * 64 + tx * 4;
            float m_old = ms[ty * 8 + i];
            float mloc = -1e30f;
            #pragma unroll
            for (int j = 0; j < 4; j++) {
                float v = (kg0 + j <= qg) ? s[i][j] * scale : -1e30f;
                s[i][j] = v;
                mloc = fmaxf(mloc, v);
            }
            #pragma unroll
            for (int mk = 1; mk < 16; mk <<= 1)
                mloc = fmaxf(mloc, __shfl_xor_sync(0xffffffffu, mloc, mk));
            float mx = fmaxf(m_old, mloc);
            float psum = 0.f;
            #pragma unroll
            for (int j = 0; j < 4; j++) {
                float p = __expf(s[i][j] - mx);
                s[i][j] = p;
                psum += p;
            }
            #pragma unroll
            for (int mk = 1; mk < 16; mk <<= 1)
                psum += __shfl_xor_sync(0xffffffffu, psum, mk);
            alpha[i] = __expf(m_old - mx);
            if (tx == 0) {
                ls[ty * 8 + i] = ls[ty * 8 + i] * alpha[i] + psum;
                ms[ty * 8 + i] = mx;
            }
            #pragma unroll
            for (int j = 0; j < 4; j++)
                Ps[(ty * 8 + i) * 68 + tx * 4 + j] = s[i][j];
        }
        __syncthreads();

        // O = O * alpha + P @ V
        #pragma unroll
        for (int i = 0; i < 8; i++)
            #pragma unroll
            for (int j = 0; j < 4; j++) O[i][j] *= alpha[i];
        #pragma unroll 4
        for (int k = 0; k < 64; k++) {
            float4 vv = *(const float4*)&Vt[k * 68 + tx * 4];
            float pv[8];
            #pragma unroll
            for (int i = 0; i < 8; i++) pv[i] = Ps[(ty * 8 + i) * 68 + k];
            #pragma unroll
            for (int i = 0; i < 8; i++) {
                O[i][0] += pv[i] * vv.x;
                O[i][1] += pv[i] * vv.y;
                O[i][2] += pv[i] * vv.z;
                O[i][3] += pv[i] * vv.w;
            }
        }
    }

    // Epilogue: divide by l, store fp16
    #pragma unroll
    for (int i = 0; i < 8; i++) {
        int q = ty * 8 + i;
        float invl = 1.0f / ls[q];
        size_t off = (size_t)(b * T_ + q0 + q) * E_ + h * D_ + tx * 4;
        #pragma unroll
        for (int j = 0; j < 4; j++)
            y[off + j] = __float2half_rn(O[i][j] * invl);
    }
}

// ---------------------------------------------------------------------------
// HMMA fp16x2 GEMM: C[M,N] = A[M,K] @ W[N,K]^T
//   A single fp16, W split (Bhi, Blo); C = A*Bh + A*Bl in fp32 regs.
//   CTA tile 128x128, K-chunks of 64, 3-stage cp.async pipeline.
//   Stage layout: A (16KB) | Bh (16KB) | Bl (16KB) = 48KB; 3 stages = 144KB.
// ---------------------------------------------------------------------------
#define GEMM_STAGE_BYTES 49152
#define GEMM_SMEM_BYTES (3 * GEMM_STAGE_BYTES)

__device__ __forceinline__ void load_row8(uint32_t smem_tile,
                                          const __half* __restrict__ g,
                                          int row0, int K, int k0, int r) {
    const char* gp = (const char*)(g + (size_t)(row0 + r) * K + k0);
    uint32_t rb = (uint32_t)r * 128;
    #pragma unroll
    for (int j = 0; j < 8; j++)
        cp_async16(smem_tile + SWZ128(rb + j * 16), gp + j * 16);
}

template<bool GELU, bool RES, bool OUT32>
__global__ void __launch_bounds__(256, 1)
gemm_hmma_kernel(const __half* __restrict__ A,
                 const __half* __restrict__ Bhi, const __half* __restrict__ Blo,
                 const float* __restrict__ R, float* __restrict__ Cf,
                 __half* __restrict__ Ch,
                 int N, int K) {
    extern __shared__ char smem[];
    const uint32_t sb = smem_u32(smem);

    const int tid = threadIdx.x;
    const int lane = tid & 31;
    const int wid = tid >> 5;
    const int wm = (wid >> 2) * 64;
    const int wn = (wid & 3) * 32;
    const int m0 = blockIdx.y * 128;
    const int n0 = blockIdx.x * 128;
    const int nchunks = K >> 6;

    const int lr = tid & 127;
    const bool lowhalf = tid < 128;

    float acc[4][4][4];
    #pragma unroll
    for (int i = 0; i < 4; i++)
        #pragma unroll
        for (int j = 0; j < 4; j++)
            #pragma unroll
            for (int q = 0; q < 4; q++) acc[i][j][q] = 0.f;

    // preload chunks 0,1 into stages 0,1
    // threads 0..127: A row lr + Bl row lr; threads 128..255: Bh row lr
    {
        uint32_t st = sb;
        if (lowhalf) {
            load_row8(st + 0,     A,   m0, K, 0, lr);
            load_row8(st + 32768, Blo, n0, K, 0, lr);
        } else {
            load_row8(st + 16384, Bhi, n0, K, 0, lr);
        }
        cp_commit();
        if (nchunks > 1) {
            st = sb + GEMM_STAGE_BYTES;
            if (lowhalf) {
                load_row8(st + 0,     A,   m0, K, 64, lr);
                load_row8(st + 32768, Blo, n0, K, 64, lr);
            } else {
                load_row8(st + 16384, Bhi, n0, K, 64, lr);
            }
            cp_commit();
        }
    }

    const uint32_t a_row = wm + (lane & 15);
    const uint32_t a_cb  = (uint32_t)((lane >> 4) << 4);
    const uint32_t b_cb  = (uint32_t)(((lane >> 3) & 1) << 4);

    for (int c = 0; c < nchunks; c++) {
        const uint32_t st = sb + (uint32_t)(c % 3) * GEMM_STAGE_BYTES;

        if (c + 1 < nchunks) cp_wait<1>();
        else                 cp_wait<0>();
        __syncthreads();

        if (c + 2 < nchunks) {
            const uint32_t sn = sb + (uint32_t)((c + 2) % 3) * GEMM_STAGE_BYTES;
            int k0 = (c + 2) << 6;
            if (lowhalf) {
                load_row8(sn + 0,     A,   m0, K, k0, lr);
                load_row8(sn + 32768, Blo, n0, K, k0, lr);
            } else {
                load_row8(sn + 16384, Bhi, n0, K, k0, lr);
            }
            cp_commit();
        }

        const uint32_t aA = st, aBh = st + 16384, aBl = st + 32768;

        #pragma unroll
        for (int ks = 0; ks < 4; ks++) {
            const uint32_t kb = (uint32_t)ks * 32;
            uint32_t af[4][4], bh[4][2], bl[4][2];
            #pragma unroll
            for (int mi = 0; mi < 4; mi++) {
                uint32_t off = SWZ128((a_row + mi * 16) * 128 + kb + a_cb);
                ldsm_x4(af[mi], aA + off);
            }
            #pragma unroll
            for (int ni = 0; ni < 4; ni++) {
                uint32_t off = SWZ128((wn + ni * 8 + (lane & 7)) * 128 + kb + b_cb);
                ldsm_x2(bh[ni], aBh + off);
                ldsm_x2(bl[ni], aBl + off);
            }
            // term-major: 16 independent accs between same-acc reuse
            #pragma unroll
            for (int mi = 0; mi < 4; mi++)
                #pragma unroll
                for (int ni = 0; ni < 4; ni++)
                    mma16816(acc[mi][ni], af[mi], bh[ni]);
            #pragma unroll
            for (int mi = 0; mi < 4; mi++)
                #pragma unroll
                for (int ni = 0; ni < 4; ni++)
                    mma16816(acc[mi][ni], af[mi], bl[ni]);
        }
        __syncthreads();
    }

    const int er = lane >> 2;
    const int ec = (lane & 3) * 2;

    #pragma unroll
    for (int mi = 0; mi < 4; mi++) {
        #pragma unroll
        for (int ni = 0; ni < 4; ni++) {
            const int row = m0 + wm + mi * 16 + er;
            const int col = n0 + wn + ni * 8 + ec;
            float v0 = acc[mi][ni][0], v1 = acc[mi][ni][1];
            float v2 = acc[mi][ni][2], v3 = acc[mi][ni][3];
            if (RES) {
                float2 r0 = *(const float2*)(R + (size_t)row * N + col);
                float2 r1 = *(const float2*)(R + (size_t)(row + 8) * N + col);
                v0 += r0.x; v1 += r0.y; v2 += r1.x; v3 += r1.y;
            }
            if (GELU) {
                v0 = 0.5f * v0 * (1.0f + erff(v0 * 0.70710678118654752f));
                v1 = 0.5f * v1 * (1.0f + erff(v1 * 0.70710678118654752f));
                v2 = 0.5f * v2 * (1.0f + erff(v2 * 0.70710678118654752f));
                v3 = 0.5f * v3 * (1.0f + erff(v3 * 0.70710678118654752f));
            }
            if (OUT32) {
                *(float2*)(Cf + (size_t)row * N + col) = make_float2(v0, v1);
                *(float2*)(Cf + (size_t)(row + 8) * N + col) = make_float2(v2, v3);
            } else {
                __half h0 = __float2half_rn(v0), h1 = __float2half_rn(v1);
                __half h2 = __float2half_rn(v2), h3 = __float2half_rn(v3);
                *(uint32_t*)(Ch + (size_t)row * N + col) =
                    (uint32_t)__half_as_ushort(h0) | ((uint32_t)__half_as_ushort(h1) << 16);
                *(uint32_t*)(Ch + (size_t)(row + 8) * N + col) =
                    (uint32_t)__half_as_ushort(h2) | ((uint32_t)__half_as_ushort(h3) << 16);
            }
        }
    }
}

// ---------------------------------------------------------------------------
// Launch
// ---------------------------------------------------------------------------
extern "C" void kernel_launch(void* const* d_in, const int* in_sizes, int n_in,
                              void* d_out, int out_size) {
    const int*   idx    = (const int*)  d_in[0];
    const float* tok    = (const float*)d_in[1];
    const float* pos    = (const float*)d_in[2];
    const float* qkv_w  = (const float*)d_in[3];
    const float* proj_w = (const float*)d_in[4];
    const float* fc_w   = (const float*)d_in[5];
    const float* fcp_w  = (const float*)d_in[6];
    const float* ln1s   = (const float*)d_in[7];
    const float* ln1b   = (const float*)d_in[8];
    const float* ln2s   = (const float*)d_in[9];
    const float* ln2b   = (const float*)d_in[10];
    const float* lnfs   = (const float*)d_in[11];
    const float* lnfb   = (const float*)d_in[12];
    float* out = (float*)d_out;

    float *x, *qkv;
    __half *b1, *b2;
    __half *wqkvh, *wqkvl, *wprojh, *wprojl, *wfch, *wfcl, *wfcph, *wfcpl, *tokh, *tokl;
    cudaGetSymbolAddress((void**)&x,     g_x);
    cudaGetSymbolAddress((void**)&qkv,   g_qkv);
    cudaGetSymbolAddress((void**)&b1,    g_b1);
    cudaGetSymbolAddress((void**)&b2,    g_b2);
    cudaGetSymbolAddress((void**)&wqkvh, g_wqkv_h);
    cudaGetSymbolAddress((void**)&wqkvl, g_wqkv_l);
    cudaGetSymbolAddress((void**)&wprojh,g_wproj_h);
    cudaGetSymbolAddress((void**)&wprojl,g_wproj_l);
    cudaGetSymbolAddress((void**)&wfch,  g_wfc_h);
    cudaGetSymbolAddress((void**)&wfcl,  g_wfc_l);
    cudaGetSymbolAddress((void**)&wfcph, g_wfcp_h);
    cudaGetSymbolAddress((void**)&wfcpl, g_wfcp_l);
    cudaGetSymbolAddress((void**)&tokh,  g_tok_h);
    cudaGetSymbolAddress((void**)&tokl,  g_tok_l);

    cudaFuncSetAttribute(gemm_hmma_kernel<false, false, true>,
                         cudaFuncAttributeMaxDynamicSharedMemorySize, GEMM_SMEM_BYTES);
    cudaFuncSetAttribute(gemm_hmma_kernel<false, true, true>,
                         cudaFuncAttributeMaxDynamicSharedMemorySize, GEMM_SMEM_BYTES);
    cudaFuncSetAttribute(gemm_hmma_kernel<true, false, false>,
                         cudaFuncAttributeMaxDynamicSharedMemorySize, GEMM_SMEM_BYTES);
    cudaFuncSetAttribute(flash_attn_kernel,
                         cudaFuncAttributeMaxDynamicSharedMemorySize, FA_SMEM_BYTES);

    // weight splits (fp32 -> fp16 hi/lo)
    {
        int n4;
        n4 = L_ * QKV3 * E_ / 4;
        split_kernel<<<(n4 + 255) / 256, 256>>>(qkv_w, wqkvh, wqkvl, n4);
        n4 = L_ * E_ * E_ / 4;
        split_kernel<<<(n4 + 255) / 256, 256>>>(proj_w, wprojh, wprojl, n4);
        n4 = L_ * FF_ * E_ / 4;
        split_kernel<<<(n4 + 255) / 256, 256>>>(fc_w, wfch, wfcl, n4);
        n4 = L_ * E_ * FF_ / 4;
        split_kernel<<<(n4 + 255) / 256, 256>>>(fcp_w, wfcph, wfcpl, n4);
        n4 = V_ * E_ / 4;
        split_kernel<<<(n4 + 255) / 256, 256>>>(tok, tokh, tokl, n4);
    }

    embed_kernel<<<M_, 256>>>(idx, tok, pos, x);

    for (int l = 0; l < L_; l++) {
        lnorm_h_kernel<<<M_, 256>>>(x, ln1s + (size_t)l * E_, ln1b + (size_t)l * E_, b1);
        gemm_hmma_kernel<false, false, true><<<dim3(QKV3 / 128, M_ / 128), 256, GEMM_SMEM_BYTES>>>(
            b1, wqkvh + (size_t)l * QKV3 * E_, wqkvl + (size_t)l * QKV3 * E_,
            nullptr, qkv, nullptr, QKV3, E_);
        flash_attn_kernel<<<dim3(T_ / 128, H_, B_), 256, FA_SMEM_BYTES>>>(qkv, b1);
        gemm_hmma_kernel<false, true, true><<<dim3(E_ / 128, M_ / 128), 256, GEMM_SMEM_BYTES>>>(
            b1, wprojh + (size_t)l * E_ * E_, wprojl + (size_t)l * E_ * E_,
            x, x, nullptr, E_, E_);
        lnorm_h_kernel<<<M_, 256>>>(x, ln2s + (size_t)l * E_, ln2b + (size_t)l * E_, b1);
        gemm_hmma_kernel<true, false, false><<<dim3(FF_ / 128, M_ / 128), 256, GEMM_SMEM_BYTES>>>(
            b1, wfch + (size_t)l * FF_ * E_, wfcl + (size_t)l * FF_ * E_,
            nullptr, nullptr, b2, FF_, E_);
        gemm_hmma_kernel<false, true, true><<<dim3(E_ / 128, M_ / 128), 256, GEMM_SMEM_BYTES>>>(
            b2, wfcph + (size_t)l * E_ * FF_, wfcpl + (size_t)l * E_ * FF_,
            x, x, nullptr, E_, FF_);
    }

    lnorm_h_kernel<<<M_, 256>>>(x, lnfs, lnfb, b1);
    gemm_hmma_kernel<false, false, true><<<dim3(V_ / 128, M_ / 128), 256, GEMM_SMEM_BYTES>>>(
        b1, tokh, tokl, nullptr, out, nullptr, V_, E_);
}

// round 13
// speedup vs baseline: 6.4887x; 1.0446x over previous
#include <cuda_runtime.h>
#include <cuda_fp16.h>
#include <math.h>
#include <stdint.h>

// Problem constants
#define V_   32000
#define E_   1024
#define L_   8
#define H_   16
#define B_   2
#define T_   1024
#define D_   64
#define M_   (B_ * T_)      // 2048 rows
#define FF_  (4 * E_)       // 4096
#define QKV3 (3 * E_)       // 3072

// ---------------------------------------------------------------------------
// Scratch (device globals — no allocation allowed in kernel_launch)
// ---------------------------------------------------------------------------
__device__ float  g_x[M_ * E_];          // residual stream (fp32)
__device__ float  g_qkv[M_ * QKV3];      // fused QKV (fp32, for attention)
__device__ __half g_b1[M_ * E_];         // activation buf1 (fp16)
__device__ __half g_b2[M_ * FF_];        // activation buf2 (fp16, MLP hidden)
// fp16 split weights (hi + lo)
__device__ __half g_wqkv_h[L_ * QKV3 * E_];
__device__ __half g_wqkv_l[L_ * QKV3 * E_];
__device__ __half g_wproj_h[L_ * E_ * E_];
__device__ __half g_wproj_l[L_ * E_ * E_];
__device__ __half g_wfc_h[L_ * FF_ * E_];
__device__ __half g_wfc_l[L_ * FF_ * E_];
__device__ __half g_wfcp_h[L_ * E_ * FF_];
__device__ __half g_wfcp_l[L_ * E_ * FF_];
__device__ __half g_tok_h[V_ * E_];
__device__ __half g_tok_l[V_ * E_];

// ---------------------------------------------------------------------------
// PTX helpers (base-target features only: cp.async, ldmatrix, mma.sync)
// ---------------------------------------------------------------------------
__device__ __forceinline__ uint32_t smem_u32(const void* p) {
    uint32_t a;
    asm("{ .reg .u64 t; cvta.to.shared.u64 t, %1; cvt.u32.u64 %0, t; }"
        : "=r"(a) : "l"(p));
    return a;
}

#define SWZ128(o) ((o) ^ (((o) >> 3) & 0x70))

__device__ __forceinline__ void cp_async16(uint32_t dst, const void* src) {
    asm volatile("cp.async.cg.shared.global [%0], [%1], 16;\n"
                 :: "r"(dst), "l"(src) : "memory");
}
__device__ __forceinline__ void cp_commit() {
    asm volatile("cp.async.commit_group;\n" ::: "memory");
}
template <int N>
__device__ __forceinline__ void cp_wait() {
    asm volatile("cp.async.wait_group %0;\n" :: "n"(N) : "memory");
}
__device__ __forceinline__ void ldsm_x4(uint32_t* r, uint32_t addr) {
    asm volatile("ldmatrix.sync.aligned.m8n8.x4.shared.b16 {%0,%1,%2,%3}, [%4];"
                 : "=r"(r[0]), "=r"(r[1]), "=r"(r[2]), "=r"(r[3]) : "r"(addr));
}
__device__ __forceinline__ void mma16816(float* d, const uint32_t* a,
                                         const uint32_t* b) {
    asm volatile(
        "mma.sync.aligned.m16n8k16.row.col.f32.f16.f16.f32 "
        "{%0,%1,%2,%3}, {%4,%5,%6,%7}, {%8,%9}, {%0,%1,%2,%3};"
        : "+f"(d[0]), "+f"(d[1]), "+f"(d[2]), "+f"(d[3])
        : "r"(a[0]), "r"(a[1]), "r"(a[2]), "r"(a[3]), "r"(b[0]), "r"(b[1]));
}

// ---------------------------------------------------------------------------
// Combined weight split: fp32 -> (hi, lo) fp16 for all 5 weight tensors in
// ONE launch (keeps the launch sequence short so ncu -s 5 lands on a GEMM).
// ---------------------------------------------------------------------------
struct SplitArgs {
    const float* src[5];
    __half* hi[5];
    __half* lo[5];
    int off4[6];   // prefix sums of float4 counts
};

__global__ void split_all_kernel(SplitArgs a) {
    int i = blockIdx.x * blockDim.x + threadIdx.x;
    if (i >= a.off4[5]) return;
    int s = 0;
    while (s < 4 && i >= a.off4[s + 1]) s++;
    int k = i - a.off4[s];

    float4 v = ((const float4*)a.src[s])[k];
    __half h0 = __float2half_rn(v.x), h1 = __float2half_rn(v.y);
    __half h2 = __float2half_rn(v.z), h3 = __float2half_rn(v.w);
    __half l0 = __float2half_rn(v.x - __half2float(h0));
    __half l1 = __float2half_rn(v.y - __half2float(h1));
    __half l2 = __float2half_rn(v.z - __half2float(h2));
    __half l3 = __float2half_rn(v.w - __half2float(h3));
    uint32_t hp0 = (uint32_t)__half_as_ushort(h0) | ((uint32_t)__half_as_ushort(h1) << 16);
    uint32_t hp1 = (uint32_t)__half_as_ushort(h2) | ((uint32_t)__half_as_ushort(h3) << 16);
    uint32_t lp0 = (uint32_t)__half_as_ushort(l0) | ((uint32_t)__half_as_ushort(l1) << 16);
    uint32_t lp1 = (uint32_t)__half_as_ushort(l2) | ((uint32_t)__half_as_ushort(l3) << 16);
    ((uint2*)a.hi[s])[k] = make_uint2(hp0, hp1);
    ((uint2*)a.lo[s])[k] = make_uint2(lp0, lp1);
}

// ---------------------------------------------------------------------------
// Embedding (fp32 residual stream)
// ---------------------------------------------------------------------------
__global__ void embed_kernel(const int* __restrict__ idx,
                             const float* __restrict__ tok,
                             const float* __restrict__ pos,
                             float* __restrict__ x) {
    int row = blockIdx.x;
    int t = row % T_;
    int id = idx[row];
    const float* tr = tok + (size_t)id * E_;
    const float* pr = pos + (size_t)t * E_;
    float* xr = x + (size_t)row * E_;
    for (int i = threadIdx.x; i < E_; i += blockDim.x)
        xr[i] = tr[i] + pr[i];
}

// ---------------------------------------------------------------------------
// LayerNorm -> fp16 output
// ---------------------------------------------------------------------------
__global__ void lnorm_h_kernel(const float* __restrict__ x,
                               const float* __restrict__ s,
                               const float* __restrict__ b,
                               __half* __restrict__ o) {
    int row = blockIdx.x;
    const float* xr = x + (size_t)row * E_;
    __shared__ float red[256];
    int tid = threadIdx.x;

    float sum = 0.f;
    for (int i = tid; i < E_; i += 256) sum += xr[i];
    red[tid] = sum;
    __syncthreads();
    for (int off = 128; off > 0; off >>= 1) {
        if (tid < off) red[tid] += red[tid + off];
        __syncthreads();
    }
    float mu = red[0] * (1.0f / E_);
    __syncthreads();

    float vs = 0.f;
    for (int i = tid; i < E_; i += 256) { float d = xr[i] - mu; vs += d * d; }
    red[tid] = vs;
    __syncthreads();
    for (int off = 128; off > 0; off >>= 1) {
        if (tid < off) red[tid] += red[tid + off];
        __syncthreads();
    }
    float inv = rsqrtf(red[0] * (1.0f / E_) + 1e-5f);

    for (int i = tid; i < E_; i += 256) {
        float v = (xr[i] - mu) * inv * s[i] + b[i];
        o[(size_t)row * E_ + i] = __float2half_rn(v);
    }
}

// ---------------------------------------------------------------------------
// Flash attention (fp32, smem-tiled, warp-parallel online softmax) -> fp16
// Grid: (qt=T/128, h, b). Block: 256 threads = 16x16.
// ---------------------------------------------------------------------------
#define FA_SMEM_FLOATS (64*132 + 64*68 + 64*68 + 128*68 + 2*128)
#define FA_SMEM_BYTES  (FA_SMEM_FLOATS * 4)

__global__ void __launch_bounds__(256, 1)
flash_attn_kernel(const float* __restrict__ qkv, __half* __restrict__ y) {
    extern __shared__ float fs[];
    float* Qt = fs;                    // [64][132] d-major Q
    float* Kt = Qt + 64 * 132;         // [64][68]  d-major K
    float* Vt = Kt + 64 * 68;          // [64][68]  k-major V
    float* Ps = Vt + 64 * 68;          // [128][68] probabilities
    float* ms = Ps + 128 * 68;         // [128] running max
    float* ls = ms + 128;              // [128] running sum

    const int qt = blockIdx.x, h = blockIdx.y, b = blockIdx.z;
    const int tid = threadIdx.x;
    const int tx = tid & 15, ty = tid >> 4;
    const int q0 = qt * 128;

    const float* qbase = qkv + (size_t)b * T_ * QKV3 + h * D_;
    const float* kbase = qbase + E_;
    const float* vbase = qbase + 2 * E_;

    {
        int qr = tid >> 1;
        int j0 = (tid & 1) * 8;
        const float4* src = (const float4*)(qbase + (size_t)(q0 + qr) * QKV3);
        #pragma unroll
        for (int j = 0; j < 8; j++) {
            float4 v = src[j0 + j];
            int d = (j0 + j) * 4;
            Qt[(d + 0) * 132 + qr] = v.x;
            Qt[(d + 1) * 132 + qr] = v.y;
            Qt[(d + 2) * 132 + qr] = v.z;
            Qt[(d + 3) * 132 + qr] = v.w;
        }
    }
    if (tid < 128) { ms[tid] = -1e30f; ls[tid] = 0.f; }

    float O[8][4] = {};
    const int ntiles = 2 * qt + 2;
    const float scale = 0.125f;

    for (int kt = 0; kt < ntiles; kt++) {
        __syncthreads();
        {
            int kr = tid >> 2;
            int j0 = (tid & 3) * 4;
            const float4* ksrc = (const float4*)(kbase + (size_t)(kt * 64 + kr) * QKV3);
            const float4* vsrc = (const float4*)(vbase + (size_t)(kt * 64 + kr) * QKV3);
            #pragma unroll
            for (int j = 0; j < 4; j++) {
                float4 kv = ksrc[j0 + j];
                int d = (j0 + j) * 4;
                Kt[(d + 0) * 68 + kr] = kv.x;
                Kt[(d + 1) * 68 + kr] = kv.y;
                Kt[(d + 2) * 68 + kr] = kv.z;
                Kt[(d + 3) * 68 + kr] = kv.w;
                float4 vv = vsrc[j0 + j];
                *(float4*)&Vt[kr * 68 + d] = vv;
            }
        }
        __syncthreads();

        float s[8][4] = {};
        #pragma unroll 4
        for (int d = 0; d < 64; d++) {
            float4 qa = *(const float4*)&Qt[d * 132 + ty * 8];
            float4 qb = *(const float4*)&Qt[d * 132 + ty * 8 + 4];
            float4 kv = *(const float4*)&Kt[d * 68 + tx * 4];
            float qv[8] = {qa.x, qa.y, qa.z, qa.w, qb.x, qb.y, qb.z, qb.w};
            float kk[4] = {kv.x, kv.y, kv.z, kv.w};
            #pragma unroll
            for (int i = 0; i < 8; i++)
                #pragma unroll
                for (int j = 0; j < 4; j++)
                    s[i][j] += qv[i] * kk[j];
        }

        float alpha[8];
        #pragma unroll
        for (int i = 0; i < 8; i++) {
            const int qg = q0 + ty * 8 + i;
            const int kg0 = kt * 64 + tx * 4;
            float m_old = ms[ty * 8 + i];
            float mloc = -1e30f;
            #pragma unroll
            for (int j = 0; j < 4; j++) {
                float v = (kg0 + j <= qg) ? s[i][j] * scale : -1e30f;
                s[i][j] = v;
                mloc = fmaxf(mloc, v);
            }
            #pragma unroll
            for (int mk = 1; mk < 16; mk <<= 1)
                mloc = fmaxf(mloc, __shfl_xor_sync(0xffffffffu, mloc, mk));
            float mx = fmaxf(m_old, mloc);
            float psum = 0.f;
            #pragma unroll
            for (int j = 0; j < 4; j++) {
                float p = __expf(s[i][j] - mx);
                s[i][j] = p;
                psum += p;
            }
            #pragma unroll
            for (int mk = 1; mk < 16; mk <<= 1)
                psum += __shfl_xor_sync(0xffffffffu, psum, mk);
            alpha[i] = __expf(m_old - mx);
            if (tx == 0) {
                ls[ty * 8 + i] = ls[ty * 8 + i] * alpha[i] + psum;
                ms[ty * 8 + i] = mx;
            }
            #pragma unroll
            for (int j = 0; j < 4; j++)
                Ps[(ty * 8 + i) * 68 + tx * 4 + j] = s[i][j];
        }
        __syncthreads();

        #pragma unroll
        for (int i = 0; i < 8; i++)
            #pragma unroll
            for (int j = 0; j < 4; j++) O[i][j] *= alpha[i];
        #pragma unroll 4
        for (int k = 0; k < 64; k++) {
            float4 vv = *(const float4*)&Vt[k * 68 + tx * 4];
            float pv[8];
            #pragma unroll
            for (int i = 0; i < 8; i++) pv[i] = Ps[(ty * 8 + i) * 68 + k];
            #pragma unroll
            for (int i = 0; i < 8; i++) {
                O[i][0] += pv[i] * vv.x;
                O[i][1] += pv[i] * vv.y;
                O[i][2] += pv[i] * vv.z;
                O[i][3] += pv[i] * vv.w;
            }
        }
    }

    #pragma unroll
    for (int i = 0; i < 8; i++) {
        int q = ty * 8 + i;
        float invl = 1.0f / ls[q];
        size_t off = (size_t)(b * T_ + q0 + q) * E_ + h * D_ + tx * 4;
        #pragma unroll
        for (int j = 0; j < 4; j++)
            y[off + j] = __float2half_rn(O[i][j] * invl);
    }
}

// ---------------------------------------------------------------------------
// HMMA fp16x2 GEMM: C[M,N] = A[M,K] @ W[N,K]^T
//   A single fp16, W split (Bhi, Blo); C = A*Bh + A*Bl in fp32 regs.
//   CTA tile 128x128, K-chunks of 64, 2-stage pipeline, 96KB smem ->
//   2 CTAs/SM (4 warps/SMSP) for latency hiding. B loaded via ldmatrix.x4
//   (2 n8 blocks per instruction), B frags reused across hi/lo terms.
// ---------------------------------------------------------------------------
#define GEMM_STAGE_BYTES 49152
#define GEMM_SMEM_BYTES (2 * GEMM_STAGE_BYTES)   // 96 KB

__device__ __forceinline__ void load_row8(uint32_t smem_tile,
                                          const __half* __restrict__ g,
                                          int row0, int K, int k0, int r) {
    const char* gp = (const char*)(g + (size_t)(row0 + r) * K + k0);
    uint32_t rb = (uint32_t)r * 128;
    #pragma unroll
    for (int j = 0; j < 8; j++)
        cp_async16(smem_tile + SWZ128(rb + j * 16), gp + j * 16);
}

template<bool GELU, bool RES, bool OUT32>
__global__ void __launch_bounds__(256, 2)
gemm_hmma_kernel(const __half* __restrict__ A,
                 const __half* __restrict__ Bhi, const __half* __restrict__ Blo,
                 const float* __restrict__ R, float* __restrict__ Cf,
                 __half* __restrict__ Ch,
                 int N, int K) {
    extern __shared__ char smem[];
    const uint32_t sb = smem_u32(smem);

    const int tid = threadIdx.x;
    const int lane = tid & 31;
    const int wid = tid >> 5;
    const int wm = (wid >> 2) * 64;
    const int wn = (wid & 3) * 32;
    const int m0 = blockIdx.y * 128;
    const int n0 = blockIdx.x * 128;
    const int nchunks = K >> 6;

    const int lr = tid & 127;
    const bool lowhalf = tid < 128;

    float acc[4][4][4];
    #pragma unroll
    for (int i = 0; i < 4; i++)
        #pragma unroll
        for (int j = 0; j < 4; j++)
            #pragma unroll
            for (int q = 0; q < 4; q++) acc[i][j][q] = 0.f;

    // preload chunk 0 into stage 0
    if (lowhalf) {
        load_row8(sb + 0,     A,   m0, K, 0, lr);
        load_row8(sb + 32768, Blo, n0, K, 0, lr);
    } else {
        load_row8(sb + 16384, Bhi, n0, K, 0, lr);
    }
    cp_commit();

    // ldmatrix lane addressing
    const uint32_t a_row = wm + (lane & 15);
    const uint32_t a_cb  = (uint32_t)((lane >> 4) << 4);
    // B x4: lanes 0-7 rows n+0..7 @kb, 8-15 rows n+0..7 @kb+16,
    //       16-23 rows n+8..15 @kb, 24-31 rows n+8..15 @kb+16
    const uint32_t b_row16 = wn + ((lane >> 4) << 3) + (lane & 7);
    const uint32_t b_cb    = (uint32_t)(((lane >> 3) & 1) << 4);

    for (int c = 0; c < nchunks; c++) {
        const uint32_t st = sb + (uint32_t)(c & 1) * GEMM_STAGE_BYTES;

        cp_wait<0>();
        __syncthreads();

        if (c + 1 < nchunks) {
            const uint32_t sn = sb + (uint32_t)((c + 1) & 1) * GEMM_STAGE_BYTES;
            int k0 = (c + 1) << 6;
            if (lowhalf) {
                load_row8(sn + 0,     A,   m0, K, k0, lr);
                load_row8(sn + 32768, Blo, n0, K, k0, lr);
            } else {
                load_row8(sn + 16384, Bhi, n0, K, k0, lr);
            }
            cp_commit();
        }

        const uint32_t aA = st, aBh = st + 16384, aBl = st + 32768;

        #pragma unroll
        for (int ks = 0; ks < 4; ks++) {
            const uint32_t kb = (uint32_t)ks * 32;
            uint32_t af[4][4], breg[8];
            #pragma unroll
            for (int mi = 0; mi < 4; mi++) {
                uint32_t off = SWZ128((a_row + mi * 16) * 128 + kb + a_cb);
                ldsm_x4(af[mi], aA + off);
            }
            // term hi
            #pragma unroll
            for (int nj = 0; nj < 2; nj++) {
                uint32_t off = SWZ128((b_row16 + nj * 16) * 128 + kb + b_cb);
                ldsm_x4(&breg[nj * 4], aBh + off);
            }
            #pragma unroll
            for (int mi = 0; mi < 4; mi++)
                #pragma unroll
                for (int ni = 0; ni < 4; ni++)
                    mma16816(acc[mi][ni], af[mi], &breg[ni * 2]);
            // term lo (reuse breg)
            #pragma unroll
            for (int nj = 0; nj < 2; nj++) {
                uint32_t off = SWZ128((b_row16 + nj * 16) * 128 + kb + b_cb);
                ldsm_x4(&breg[nj * 4], aBl + off);
            }
            #pragma unroll
            for (int mi = 0; mi < 4; mi++)
                #pragma unroll
                for (int ni = 0; ni < 4; ni++)
                    mma16816(acc[mi][ni], af[mi], &breg[ni * 2]);
        }
        __syncthreads();
    }

    const int er = lane >> 2;
    const int ec = (lane & 3) * 2;

    #pragma unroll
    for (int mi = 0; mi < 4; mi++) {
        #pragma unroll
        for (int ni = 0; ni < 4; ni++) {
            const int row = m0 + wm + mi * 16 + er;
            const int col = n0 + wn + ni * 8 + ec;
            float v0 = acc[mi][ni][0], v1 = acc[mi][ni][1];
            float v2 = acc[mi][ni][2], v3 = acc[mi][ni][3];
            if (RES) {
                float2 r0 = *(const float2*)(R + (size_t)row * N + col);
                float2 r1 = *(const float2*)(R + (size_t)(row + 8) * N + col);
                v0 += r0.x; v1 += r0.y; v2 += r1.x; v3 += r1.y;
            }
            if (GELU) {
                v0 = 0.5f * v0 * (1.0f + erff(v0 * 0.70710678118654752f));
                v1 = 0.5f * v1 * (1.0f + erff(v1 * 0.70710678118654752f));
                v2 = 0.5f * v2 * (1.0f + erff(v2 * 0.70710678118654752f));
                v3 = 0.5f * v3 * (1.0f + erff(v3 * 0.70710678118654752f));
            }
            if (OUT32) {
                *(float2*)(Cf + (size_t)row * N + col) = make_float2(v0, v1);
                *(float2*)(Cf + (size_t)(row + 8) * N + col) = make_float2(v2, v3);
            } else {
                __half h0 = __float2half_rn(v0), h1 = __float2half_rn(v1);
                __half h2 = __float2half_rn(v2), h3 = __float2half_rn(v3);
                *(uint32_t*)(Ch + (size_t)row * N + col) =
                    (uint32_t)__half_as_ushort(h0) | ((uint32_t)__half_as_ushort(h1) << 16);
                *(uint32_t*)(Ch + (size_t)(row + 8) * N + col) =
                    (uint32_t)__half_as_ushort(h2) | ((uint32_t)__half_as_ushort(h3) << 16);
            }
        }
    }
}

// ---------------------------------------------------------------------------
// Launch
// ---------------------------------------------------------------------------
extern "C" void kernel_launch(void* const* d_in, const int* in_sizes, int n_in,
                              void* d_out, int out_size) {
    const int*   idx    = (const int*)  d_in[0];
    const float* tok    = (const float*)d_in[1];
    const float* pos    = (const float*)d_in[2];
    const float* qkv_w  = (const float*)d_in[3];
    const float* proj_w = (const float*)d_in[4];
    const float* fc_w   = (const float*)d_in[5];
    const float* fcp_w  = (const float*)d_in[6];
    const float* ln1s   = (const float*)d_in[7];
    const float* ln1b   = (const float*)d_in[8];
    const float* ln2s   = (const float*)d_in[9];
    const float* ln2b   = (const float*)d_in[10];
    const float* lnfs   = (const float*)d_in[11];
    const float* lnfb   = (const float*)d_in[12];
    float* out = (float*)d_out;

    float *x, *qkv;
    __half *b1, *b2;
    __half *wqkvh, *wqkvl, *wprojh, *wprojl, *wfch, *wfcl, *wfcph, *wfcpl, *tokh, *tokl;
    cudaGetSymbolAddress((void**)&x,     g_x);
    cudaGetSymbolAddress((void**)&qkv,   g_qkv);
    cudaGetSymbolAddress((void**)&b1,    g_b1);
    cudaGetSymbolAddress((void**)&b2,    g_b2);
    cudaGetSymbolAddress((void**)&wqkvh, g_wqkv_h);
    cudaGetSymbolAddress((void**)&wqkvl, g_wqkv_l);
    cudaGetSymbolAddress((void**)&wprojh,g_wproj_h);
    cudaGetSymbolAddress((void**)&wprojl,g_wproj_l);
    cudaGetSymbolAddress((void**)&wfch,  g_wfc_h);
    cudaGetSymbolAddress((void**)&wfcl,  g_wfc_l);
    cudaGetSymbolAddress((void**)&wfcph, g_wfcp_h);
    cudaGetSymbolAddress((void**)&wfcpl, g_wfcp_l);
    cudaGetSymbolAddress((void**)&tokh,  g_tok_h);
    cudaGetSymbolAddress((void**)&tokl,  g_tok_l);

    cudaFuncSetAttribute(gemm_hmma_kernel<false, false, true>,
                         cudaFuncAttributeMaxDynamicSharedMemorySize, GEMM_SMEM_BYTES);
    cudaFuncSetAttribute(gemm_hmma_kernel<false, true, true>,
                         cudaFuncAttributeMaxDynamicSharedMemorySize, GEMM_SMEM_BYTES);
    cudaFuncSetAttribute(gemm_hmma_kernel<true, false, false>,
                         cudaFuncAttributeMaxDynamicSharedMemorySize, GEMM_SMEM_BYTES);
    cudaFuncSetAttribute(flash_attn_kernel,
                         cudaFuncAttributeMaxDynamicSharedMemorySize, FA_SMEM_BYTES);

    // Combined weight split (launch 0)
    {
        SplitArgs a;
        a.src[0] = qkv_w;  a.hi[0] = wqkvh;  a.lo[0] = wqkvl;
        a.src[1] = proj_w; a.hi[1] = wprojh; a.lo[1] = wprojl;
        a.src[2] = fc_w;   a.hi[2] = wfch;   a.lo[2] = wfcl;
        a.src[3] = fcp_w;  a.hi[3] = wfcph;  a.lo[3] = wfcpl;
        a.src[4] = tok;    a.hi[4] = tokh;   a.lo[4] = tokl;
        int n0 = L_ * QKV3 * E_ / 4, n1 = L_ * E_ * E_ / 4;
        int n2 = L_ * FF_ * E_ / 4,  n3 = L_ * E_ * FF_ / 4, n4c = V_ * E_ / 4;
        a.off4[0] = 0;
        a.off4[1] = n0;
        a.off4[2] = n0 + n1;
        a.off4[3] = n0 + n1 + n2;
        a.off4[4] = n0 + n1 + n2 + n3;
        a.off4[5] = n0 + n1 + n2 + n3 + n4c;
        int total = a.off4[5];
        split_all_kernel<<<(total + 255) / 256, 256>>>(a);
    }

    embed_kernel<<<M_, 256>>>(idx, tok, pos, x);   // launch 1

    for (int l = 0; l < L_; l++) {
        // launches 2.. : ln, qkv-gemm, attn, proj-gemm(idx 5 on l=0), ...
        lnorm_h_kernel<<<M_, 256>>>(x, ln1s + (size_t)l * E_, ln1b + (size_t)l * E_, b1);
        gemm_hmma_kernel<false, false, true><<<dim3(QKV3 / 128, M_ / 128), 256, GEMM_SMEM_BYTES>>>(
            b1, wqkvh + (size_t)l * QKV3 * E_, wqkvl + (size_t)l * QKV3 * E_,
            nullptr, qkv, nullptr, QKV3, E_);
        flash_attn_kernel<<<dim3(T_ / 128, H_, B_), 256, FA_SMEM_BYTES>>>(qkv, b1);
        gemm_hmma_kernel<false, true, true><<<dim3(E_ / 128, M_ / 128), 256, GEMM_SMEM_BYTES>>>(
            b1, wprojh + (size_t)l * E_ * E_, wprojl + (size_t)l * E_ * E_,
            x, x, nullptr, E_, E_);
        lnorm_h_kernel<<<M_, 256>>>(x, ln2s + (size_t)l * E_, ln2b + (size_t)l * E_, b1);
        gemm_hmma_kernel<true, false, false><<<dim3(FF_ / 128, M_ / 128), 256, GEMM_SMEM_BYTES>>>(
            b1, wfch + (size_t)l * FF_ * E_, wfcl + (size_t)l * FF_ * E_,
            nullptr, nullptr, b2, FF_, E_);
        gemm_hmma_kernel<false, true, true><<<dim3(E_ / 128, M_ / 128), 256, GEMM_SMEM_BYTES>>>(
            b2, wfcph + (size_t)l * E_ * FF_, wfcpl + (size_t)l * E_ * FF_,
            x, x, nullptr, E_, FF_);
    }

    lnorm_h_kernel<<<M_, 256>>>(x, lnfs, lnfb, b1);
    gemm_hmma_kernel<false, false, true><<<dim3(V_ / 128, M_ / 128), 256, GEMM_SMEM_BYTES>>>(
        b1, tokh, tokl, nullptr, out, nullptr, V_, E_);
}